// round 11
// baseline (speedup 1.0000x reference)
#include <cuda_runtime.h>
#include <cstddef>
#include <cstdint>

// Problem constants
#define B_ 2
#define L_ 2048
#define DM 1024
#define H_ 16
#define DH 64
#define MROWS (B_ * L_)   // 4096

// ---------------- scratch (no allocation allowed) ----------------
__device__ float g_q_hi[MROWS * DM], g_q_lo[MROWS * DM];
__device__ float g_k_hi[MROWS * DM], g_k_lo[MROWS * DM];
__device__ float g_v_hi[MROWS * DM], g_v_lo[MROWS * DM];
__device__ float g_Wq_hi[DM * DM], g_Wq_lo[DM * DM];
__device__ float g_Wk_hi[DM * DM], g_Wk_lo[DM * DM];
__device__ float g_Wv_hi[DM * DM], g_Wv_lo[DM * DM];
__device__ float g_Wo_hi[DM * DM], g_Wo_lo[DM * DM];
__device__ float g_qh_hi[MROWS * DM], g_qh_lo[MROWS * DM];
__device__ float g_kh_hi[MROWS * DM], g_kh_lo[MROWS * DM];
__device__ float g_vh_hi[MROWS * DM], g_vh_lo[MROWS * DM];
__device__ float g_att_hi[MROWS * DM], g_att_lo[MROWS * DM];

// ---------------- tf32 helpers ----------------
__device__ __forceinline__ unsigned f2tf32(float x) {
    unsigned r;
    asm("cvt.rna.tf32.f32 %0, %1;" : "=r"(r) : "f"(x));
    return r;
}
__device__ __forceinline__ float tf32f(float x) {
    return __uint_as_float(f2tf32(x));
}
__device__ __forceinline__ void splitf(float x, float& h, float& l) {
    h = tf32f(x);
    l = __uint_as_float(f2tf32(x - h));
}
__device__ __forceinline__ void mma_tf32(
    float& c0, float& c1, float& c2, float& c3,
    unsigned a0, unsigned a1, unsigned a2, unsigned a3,
    unsigned b0, unsigned b1)
{
    asm volatile(
        "mma.sync.aligned.m16n8k8.row.col.f32.tf32.tf32.f32 "
        "{%0,%1,%2,%3}, {%4,%5,%6,%7}, {%8,%9}, {%0,%1,%2,%3};"
        : "+f"(c0), "+f"(c1), "+f"(c2), "+f"(c3)
        : "r"(a0), "r"(a1), "r"(a2), "r"(a3), "r"(b0), "r"(b1));
}

// ---------------- cp.async helpers ----------------
__device__ __forceinline__ void cp_async16(void* smem_ptr, const void* gptr) {
    unsigned saddr = (unsigned)__cvta_generic_to_shared(smem_ptr);
    asm volatile("cp.async.cg.shared.global [%0], [%1], 16;\n"
                 :: "r"(saddr), "l"(gptr));
}
__device__ __forceinline__ void cp_commit() {
    asm volatile("cp.async.commit_group;\n");
}
template<int N> __device__ __forceinline__ void cp_wait() {
    asm volatile("cp.async.wait_group %0;\n" :: "n"(N));
}

// ---------------- batched split pre-pass ----------------
struct SplitEnt { const float* s; float* h; float* l; int n4; };
struct SplitBatch { SplitEnt e[7]; };

__global__ __launch_bounds__(256) void split7(SplitBatch sb) {
    const SplitEnt& e = sb.e[blockIdx.z];
    int i = blockIdx.x * blockDim.x + threadIdx.x;
    if (i >= e.n4) return;
    float4 x = ((const float4*)e.s)[i];
    float4 h4, l4;
    splitf(x.x, h4.x, l4.x); splitf(x.y, h4.y, l4.y);
    splitf(x.z, h4.z, l4.z); splitf(x.w, h4.w, l4.w);
    ((float4*)e.h)[i] = h4;
    ((float4*)e.l)[i] = l4;
}

// ---------------- 3xTF32 GEMM, pre-split operands, batched, 512 thr ----------------
// C = A * B. 128x128x32 CTA tile, 512 threads = 16 warps (4m x 4n), warp tile 32x32.
#define GBM 128
#define GBN 128
#define GBK 32
#define AS_STR 36
#define BS_STR 136
#define A_TILE (GBM * AS_STR)
#define B_TILE (GBK * BS_STR)
#define STAGE_F (2 * (A_TILE + B_TILE))
#define GEMM_SMEM (2 * STAGE_F * 4)          // 143360 B

struct GemmEnt { const float *Ah, *Al, *Bh, *Bl; float *C0, *C1; };
struct GemmBatch { GemmEnt e[3]; int writeSplit; };

__global__ __launch_bounds__(512) void gemm_ps(GemmBatch gb, int M, int N, int K)
{
    extern __shared__ float smg[];
    const GemmEnt& P = gb.e[blockIdx.z];

    int tid  = threadIdx.x;
    int lane = tid & 31;
    int warp = tid >> 5;
    int wm = warp & 3;       // 0..3
    int wn = warp >> 2;      // 0..3
    int g  = lane >> 2;
    int tg = lane & 3;
    int rowBase = blockIdx.y * GBM;
    int colBase = blockIdx.x * GBN;

    auto load_tile = [&](int k0, int s) {
        float* AsH = smg + s * STAGE_F;
        float* AsL = AsH + A_TILE;
        float* BsH = AsL + A_TILE;
        float* BsL = BsH + B_TILE;
#pragma unroll
        for (int it = 0; it < 2; it++) {
            int idx = tid + it * 512;           // 0..1023
            int ar = idx >> 3, ac4 = idx & 7;   // A: 128 x 8 float4
            size_t ga = (size_t)(rowBase + ar) * K + k0 + ac4 * 4;
            cp_async16(&AsH[ar * AS_STR + ac4 * 4], P.Ah + ga);
            cp_async16(&AsL[ar * AS_STR + ac4 * 4], P.Al + ga);
            int br = idx >> 5, bc4 = idx & 31;  // B: 32 x 32 float4
            size_t gbo = (size_t)(k0 + br) * N + colBase + bc4 * 4;
            cp_async16(&BsH[br * BS_STR + bc4 * 4], P.Bh + gbo);
            cp_async16(&BsL[br * BS_STR + bc4 * 4], P.Bl + gbo);
        }
    };

    float acc[2][4][4];
#pragma unroll
    for (int mt = 0; mt < 2; mt++)
#pragma unroll
        for (int nt = 0; nt < 4; nt++)
#pragma unroll
            for (int i = 0; i < 4; i++) acc[mt][nt][i] = 0.f;

    int NT = K / GBK;
    load_tile(0, 0);
    cp_commit();

    for (int t = 0; t < NT; t++) {
        if (t + 1 < NT) load_tile((t + 1) * GBK, (t + 1) & 1);
        cp_commit();
        cp_wait<1>();
        __syncthreads();

        const float* AsH = smg + (t & 1) * STAGE_F;
        const float* AsL = AsH + A_TILE;
        const float* BsH = AsL + A_TILE;
        const float* BsL = BsH + B_TILE;

#pragma unroll
        for (int ks = 0; ks < 4; ks++) {
            int kk = ks * 8 + tg;
            unsigned afH[2][4], afL[2][4];
#pragma unroll
            for (int mt = 0; mt < 2; mt++) {
                int m = wm * 32 + mt * 16 + g;
                afH[mt][0] = __float_as_uint(AsH[m * AS_STR + kk]);
                afH[mt][1] = __float_as_uint(AsH[(m + 8) * AS_STR + kk]);
                afH[mt][2] = __float_as_uint(AsH[m * AS_STR + kk + 4]);
                afH[mt][3] = __float_as_uint(AsH[(m + 8) * AS_STR + kk + 4]);
                afL[mt][0] = __float_as_uint(AsL[m * AS_STR + kk]);
                afL[mt][1] = __float_as_uint(AsL[(m + 8) * AS_STR + kk]);
                afL[mt][2] = __float_as_uint(AsL[m * AS_STR + kk + 4]);
                afL[mt][3] = __float_as_uint(AsL[(m + 8) * AS_STR + kk + 4]);
            }
            unsigned bfH[4][2], bfL[4][2];
#pragma unroll
            for (int nt = 0; nt < 4; nt++) {
                int n = wn * 32 + nt * 8 + g;
                bfH[nt][0] = __float_as_uint(BsH[kk * BS_STR + n]);
                bfH[nt][1] = __float_as_uint(BsH[(kk + 4) * BS_STR + n]);
                bfL[nt][0] = __float_as_uint(BsL[kk * BS_STR + n]);
                bfL[nt][1] = __float_as_uint(BsL[(kk + 4) * BS_STR + n]);
            }
#pragma unroll
            for (int mt = 0; mt < 2; mt++)
#pragma unroll
                for (int nt = 0; nt < 4; nt++) {
                    float* c = acc[mt][nt];
                    mma_tf32(c[0], c[1], c[2], c[3],
                             afH[mt][0], afH[mt][1], afH[mt][2], afH[mt][3],
                             bfL[nt][0], bfL[nt][1]);
                    mma_tf32(c[0], c[1], c[2], c[3],
                             afL[mt][0], afL[mt][1], afL[mt][2], afL[mt][3],
                             bfH[nt][0], bfH[nt][1]);
                    mma_tf32(c[0], c[1], c[2], c[3],
                             afH[mt][0], afH[mt][1], afH[mt][2], afH[mt][3],
                             bfH[nt][0], bfH[nt][1]);
                }
        }
        __syncthreads();
    }

#pragma unroll
    for (int mt = 0; mt < 2; mt++) {
#pragma unroll
        for (int nt = 0; nt < 4; nt++) {
            int r0 = rowBase + wm * 32 + mt * 16 + g;
            int cc = colBase + wn * 32 + nt * 8 + 2 * tg;
            float* c = acc[mt][nt];
            if (gb.writeSplit) {
                float h0, l0, h1, l1;
                splitf(c[0], h0, l0); splitf(c[1], h1, l1);
                *(float2*)(P.C0 + (size_t)r0 * N + cc) = make_float2(h0, h1);
                *(float2*)(P.C1 + (size_t)r0 * N + cc) = make_float2(l0, l1);
                splitf(c[2], h0, l0); splitf(c[3], h1, l1);
                *(float2*)(P.C0 + (size_t)(r0 + 8) * N + cc) = make_float2(h0, h1);
                *(float2*)(P.C1 + (size_t)(r0 + 8) * N + cc) = make_float2(l0, l1);
            } else {
                *(float2*)(P.C0 + (size_t)r0 * N + cc)       = make_float2(c[0], c[1]);
                *(float2*)(P.C0 + (size_t)(r0 + 8) * N + cc) = make_float2(c[2], c[3]);
            }
        }
    }
}

// ---------------- 3xTF32 flash attention (causal), TQ=128, 8 warps ----------------
// CTA per (b, h, 128-row q tile). 256 threads = 8 warps, warp owns 16 q rows.
// K/V tiles are 64 keys wide, hi/lo planes staged via cp.async double-buffer.
#define TQ 128
#define TK 64
#define KS_STR 68
#define VS_STR 72
#define K_TILE (TK * KS_STR)
#define V_TILE (TK * VS_STR)
#define AST_F (2 * (K_TILE + V_TILE))
#define ATTN_SMEM (2 * AST_F * 4)            // 143360 B

__global__ __launch_bounds__(256) void attn_ps(
    const float* __restrict__ qhH, const float* __restrict__ qhL,
    const float* __restrict__ khH, const float* __restrict__ khL,
    const float* __restrict__ vhH, const float* __restrict__ vhL,
    float* __restrict__ attH, float* __restrict__ attL)
{
    extern __shared__ float sm[];

    int bh = blockIdx.y;
    int b = bh >> 4;
    int h = bh & 15;
    int qt = (L_ / TQ - 1) - blockIdx.x;     // heavy tiles first
    int q0 = qt * TQ;

    int tid  = threadIdx.x;
    int lane = tid & 31;
    int warp = tid >> 5;                     // 0..7
    int g  = lane >> 2;
    int tg = lane & 3;

    const size_t base = (size_t)b * L_ * DM + (size_t)h * DH;
    int r0 = q0 + warp * 16 + g;

    auto load_kv = [&](int k0, int s) {
        float* KsH = sm + s * AST_F;
        float* KsL = KsH + K_TILE;
        float* VsH = KsL + K_TILE;
        float* VsL = VsH + V_TILE;
#pragma unroll
        for (int it = 0; it < 4; it++) {
            int idx = tid + it * 256;        // 0..1023
            int row = idx >> 4, c4 = idx & 15;
            size_t go = base + (size_t)(k0 + row) * DM + c4 * 4;
            cp_async16(&KsH[row * KS_STR + c4 * 4], khH + go);
            cp_async16(&KsL[row * KS_STR + c4 * 4], khL + go);
            cp_async16(&VsH[row * VS_STR + c4 * 4], vhH + go);
            cp_async16(&VsL[row * VS_STR + c4 * 4], vhL + go);
        }
    };

    // Q fragments (hi/lo) straight from pre-split planes
    unsigned qaH[8][4], qaL[8][4];
#pragma unroll
    for (int kd = 0; kd < 8; kd++) {
        int c = kd * 8 + tg;
        size_t i0 = base + (size_t)r0 * DM + c;
        size_t i1 = base + (size_t)(r0 + 8) * DM + c;
        qaH[kd][0] = __float_as_uint(qhH[i0]);
        qaH[kd][1] = __float_as_uint(qhH[i1]);
        qaH[kd][2] = __float_as_uint(qhH[i0 + 4]);
        qaH[kd][3] = __float_as_uint(qhH[i1 + 4]);
        qaL[kd][0] = __float_as_uint(qhL[i0]);
        qaL[kd][1] = __float_as_uint(qhL[i1]);
        qaL[kd][2] = __float_as_uint(qhL[i0 + 4]);
        qaL[kd][3] = __float_as_uint(qhL[i1 + 4]);
    }

    float o[8][4];
#pragma unroll
    for (int nd = 0; nd < 8; nd++)
#pragma unroll
        for (int i = 0; i < 4; i++) o[nd][i] = 0.f;
    float m0 = -1e30f, m1 = -1e30f, l0s = 0.f, l1s = 0.f;

    int ntiles = 2 * qt + 2;                 // cover keys [0, q0+TQ)
    load_kv(0, 0);
    cp_commit();

    for (int t = 0; t < ntiles; t++) {
        if (t + 1 < ntiles) load_kv((t + 1) * TK, (t + 1) & 1);
        cp_commit();
        cp_wait<1>();
        __syncthreads();

        const float* KsH = sm + (t & 1) * AST_F;
        const float* KsL = KsH + K_TILE;
        const float* VsH = KsL + K_TILE;
        const float* VsL = VsH + V_TILE;
        int k0 = t * TK;

        // scores: 16 x 64 per warp
        float s[8][4];
#pragma unroll
        for (int nt = 0; nt < 8; nt++)
#pragma unroll
            for (int i = 0; i < 4; i++) s[nt][i] = 0.f;

#pragma unroll
        for (int kd = 0; kd < 8; kd++) {
            int kk = kd * 8 + tg;
#pragma unroll
            for (int nt = 0; nt < 8; nt++) {
                int nrow = nt * 8 + g;
                unsigned bH0 = __float_as_uint(KsH[nrow * KS_STR + kk]);
                unsigned bH1 = __float_as_uint(KsH[nrow * KS_STR + kk + 4]);
                unsigned bL0 = __float_as_uint(KsL[nrow * KS_STR + kk]);
                unsigned bL1 = __float_as_uint(KsL[nrow * KS_STR + kk + 4]);
                float* c = s[nt];
                mma_tf32(c[0], c[1], c[2], c[3],
                         qaH[kd][0], qaH[kd][1], qaH[kd][2], qaH[kd][3], bL0, bL1);
                mma_tf32(c[0], c[1], c[2], c[3],
                         qaL[kd][0], qaL[kd][1], qaL[kd][2], qaL[kd][3], bH0, bH1);
                mma_tf32(c[0], c[1], c[2], c[3],
                         qaH[kd][0], qaH[kd][1], qaH[kd][2], qaH[kd][3], bH0, bH1);
            }
        }

        // causal mask: only the last two tiles can touch the diagonal
        if (t >= 2 * qt) {
#pragma unroll
            for (int nt = 0; nt < 8; nt++) {
                int col = k0 + nt * 8 + 2 * tg;
                if (col     > r0)     s[nt][0] = -1e9f;
                if (col + 1 > r0)     s[nt][1] = -1e9f;
                if (col     > r0 + 8) s[nt][2] = -1e9f;
                if (col + 1 > r0 + 8) s[nt][3] = -1e9f;
            }
        }

        // online softmax (2 rows per thread)
        float mx0 = -1e30f, mx1 = -1e30f;
#pragma unroll
        for (int nt = 0; nt < 8; nt++) {
            mx0 = fmaxf(mx0, fmaxf(s[nt][0], s[nt][1]));
            mx1 = fmaxf(mx1, fmaxf(s[nt][2], s[nt][3]));
        }
        mx0 = fmaxf(mx0, __shfl_xor_sync(0xffffffffu, mx0, 1));
        mx0 = fmaxf(mx0, __shfl_xor_sync(0xffffffffu, mx0, 2));
        mx1 = fmaxf(mx1, __shfl_xor_sync(0xffffffffu, mx1, 1));
        mx1 = fmaxf(mx1, __shfl_xor_sync(0xffffffffu, mx1, 2));

        float mn0 = fmaxf(m0, mx0), mn1 = fmaxf(m1, mx1);
        float cr0 = __expf(m0 - mn0), cr1 = __expf(m1 - mn1);
        float sum0 = 0.f, sum1 = 0.f;
#pragma unroll
        for (int nt = 0; nt < 8; nt++) {
            s[nt][0] = __expf(s[nt][0] - mn0);
            s[nt][1] = __expf(s[nt][1] - mn0);
            s[nt][2] = __expf(s[nt][2] - mn1);
            s[nt][3] = __expf(s[nt][3] - mn1);
            sum0 += s[nt][0] + s[nt][1];
            sum1 += s[nt][2] + s[nt][3];
        }
        sum0 += __shfl_xor_sync(0xffffffffu, sum0, 1);
        sum0 += __shfl_xor_sync(0xffffffffu, sum0, 2);
        sum1 += __shfl_xor_sync(0xffffffffu, sum1, 1);
        sum1 += __shfl_xor_sync(0xffffffffu, sum1, 2);
        l0s = l0s * cr0 + sum0;
        l1s = l1s * cr1 + sum1;
        m0 = mn0; m1 = mn1;

#pragma unroll
        for (int nd = 0; nd < 8; nd++) {
            o[nd][0] *= cr0; o[nd][1] *= cr0;
            o[nd][2] *= cr1; o[nd][3] *= cr1;
        }

        // PV: P(16x64) x V(64x64). Accumulator layout -> A-fragment via shfl.
        int lq = lane & ~3;
        int srcA = lq + (tg >> 1);
        int srcB = srcA + 2;
        bool odd = (tg & 1);
#pragma unroll
        for (int ks = 0; ks < 8; ks++) {
            float w00 = __shfl_sync(0xffffffffu, s[ks][0], srcA);
            float w01 = __shfl_sync(0xffffffffu, s[ks][1], srcA);
            float w02 = __shfl_sync(0xffffffffu, s[ks][2], srcA);
            float w03 = __shfl_sync(0xffffffffu, s[ks][3], srcA);
            float w10 = __shfl_sync(0xffffffffu, s[ks][0], srcB);
            float w11 = __shfl_sync(0xffffffffu, s[ks][1], srcB);
            float w12 = __shfl_sync(0xffffffffu, s[ks][2], srcB);
            float w13 = __shfl_sync(0xffffffffu, s[ks][3], srcB);
            float pa0f = odd ? w01 : w00;
            float pa1f = odd ? w03 : w02;
            float pa2f = odd ? w11 : w10;
            float pa3f = odd ? w13 : w12;
            float hF, lF;
            unsigned pH0, pL0, pH1, pL1, pH2, pL2, pH3, pL3;
            splitf(pa0f, hF, lF); pH0 = __float_as_uint(hF); pL0 = __float_as_uint(lF);
            splitf(pa1f, hF, lF); pH1 = __float_as_uint(hF); pL1 = __float_as_uint(lF);
            splitf(pa2f, hF, lF); pH2 = __float_as_uint(hF); pL2 = __float_as_uint(lF);
            splitf(pa3f, hF, lF); pH3 = __float_as_uint(hF); pL3 = __float_as_uint(lF);

            int kk = ks * 8 + tg;
#pragma unroll
            for (int nd = 0; nd < 8; nd++) {
                unsigned vH0 = __float_as_uint(VsH[kk * VS_STR + nd * 8 + g]);
                unsigned vH1 = __float_as_uint(VsH[(kk + 4) * VS_STR + nd * 8 + g]);
                unsigned vL0 = __float_as_uint(VsL[kk * VS_STR + nd * 8 + g]);
                unsigned vL1 = __float_as_uint(VsL[(kk + 4) * VS_STR + nd * 8 + g]);
                float* c = o[nd];
                mma_tf32(c[0], c[1], c[2], c[3], pH0, pH1, pH2, pH3, vL0, vL1);
                mma_tf32(c[0], c[1], c[2], c[3], pL0, pL1, pL2, pL3, vH0, vH1);
                mma_tf32(c[0], c[1], c[2], c[3], pH0, pH1, pH2, pH3, vH0, vH1);
            }
        }
        __syncthreads();
    }

    // softmax-then-scale quirk: divide by l AND by sqrt(DH)=8; write pre-split
    float inv0 = 1.f / (l0s * 8.f);
    float inv1 = 1.f / (l1s * 8.f);
#pragma unroll
    for (int nd = 0; nd < 8; nd++) {
        int cc = nd * 8 + 2 * tg;
        size_t i0 = base + (size_t)r0 * DM + cc;
        size_t i1 = base + (size_t)(r0 + 8) * DM + cc;
        float h0, l0, h1, l1;
        splitf(o[nd][0] * inv0, h0, l0); splitf(o[nd][1] * inv0, h1, l1);
        *(float2*)(attH + i0) = make_float2(h0, h1);
        *(float2*)(attL + i0) = make_float2(l0, l1);
        splitf(o[nd][2] * inv1, h0, l0); splitf(o[nd][3] * inv1, h1, l1);
        *(float2*)(attH + i1) = make_float2(h0, h1);
        *(float2*)(attL + i1) = make_float2(l0, l1);
    }
}

// ---------------- launch ----------------
extern "C" void kernel_launch(void* const* d_in, const int* in_sizes, int n_in,
                              void* d_out, int out_size)
{
    const float* q  = (const float*)d_in[0];
    const float* k  = (const float*)d_in[1];
    const float* v  = (const float*)d_in[2];
    // d_in[3] is the causal mask -> handled analytically
    const float* Wq = (const float*)d_in[4];
    const float* Wk = (const float*)d_in[5];
    const float* Wv = (const float*)d_in[6];
    const float* Wo = (const float*)d_in[7];
    float* out = (float*)d_out;

    auto ga = [](const void* sym) {
        void* p; cudaGetSymbolAddress(&p, sym); return (float*)p;
    };
    float *qH = ga(g_q_hi), *qL = ga(g_q_lo);
    float *kH = ga(g_k_hi), *kL = ga(g_k_lo);
    float *vH = ga(g_v_hi), *vL = ga(g_v_lo);
    float *WqH = ga(g_Wq_hi), *WqL = ga(g_Wq_lo);
    float *WkH = ga(g_Wk_hi), *WkL = ga(g_Wk_lo);
    float *WvH = ga(g_Wv_hi), *WvL = ga(g_Wv_lo);
    float *WoH = ga(g_Wo_hi), *WoL = ga(g_Wo_lo);
    float *qhH = ga(g_qh_hi), *qhL = ga(g_qh_lo);
    float *khH = ga(g_kh_hi), *khL = ga(g_kh_lo);
    float *vhH = ga(g_vh_hi), *vhL = ga(g_vh_lo);
    float *attH = ga(g_att_hi), *attL = ga(g_att_lo);

    static int smem_set = 0;
    if (!smem_set) {
        cudaFuncSetAttribute(gemm_ps, cudaFuncAttributeMaxDynamicSharedMemorySize, GEMM_SMEM);
        cudaFuncSetAttribute(attn_ps, cudaFuncAttributeMaxDynamicSharedMemorySize, ATTN_SMEM);
        smem_set = 1;
    }

    // 1. batched split pre-pass
    SplitBatch sb;
    int n4in = MROWS * DM / 4;
    int n4w  = DM * DM / 4;
    sb.e[0] = {q,  qH,  qL,  n4in};
    sb.e[1] = {k,  kH,  kL,  n4in};
    sb.e[2] = {v,  vH,  vL,  n4in};
    sb.e[3] = {Wq, WqH, WqL, n4w};
    sb.e[4] = {Wk, WkH, WkL, n4w};
    sb.e[5] = {Wv, WvH, WvL, n4w};
    sb.e[6] = {Wo, WoH, WoL, n4w};
    split7<<<dim3(n4in / 256, 1, 7), 256>>>(sb);

    // 2. three projection GEMMs, one batched launch, split outputs
    GemmBatch gp;
    gp.writeSplit = 1;
    gp.e[0] = {qH, qL, WqH, WqL, qhH, qhL};
    gp.e[1] = {kH, kL, WkH, WkL, khH, khL};
    gp.e[2] = {vH, vL, WvH, WvL, vhH, vhL};
    gemm_ps<<<dim3(DM / GBN, MROWS / GBM, 3), 512, GEMM_SMEM>>>(gp, MROWS, DM, DM);

    // 3. attention
    attn_ps<<<dim3(L_ / TQ, B_ * H_), 256, ATTN_SMEM>>>(
        qhH, qhL, khH, khL, vhH, vhL, attH, attL);

    // 4. output GEMM, raw fp32 result
    GemmBatch go;
    go.writeSplit = 0;
    go.e[0] = {attH, attL, WoH, WoL, out, nullptr};
    go.e[1] = go.e[0];
    go.e[2] = go.e[0];
    gemm_ps<<<dim3(DM / GBN, MROWS / GBM, 1), 512, GEMM_SMEM>>>(go, MROWS, DM, DM);
}

// round 13
// speedup vs baseline: 1.0489x; 1.0489x over previous
#include <cuda_runtime.h>
#include <cstddef>
#include <cstdint>

// Problem constants
#define B_ 2
#define L_ 2048
#define DM 1024
#define H_ 16
#define DH 64
#define MROWS (B_ * L_)   // 4096

// ---------------- scratch (no allocation allowed) ----------------
__device__ float g_q_hi[MROWS * DM], g_q_lo[MROWS * DM];
__device__ float g_k_hi[MROWS * DM], g_k_lo[MROWS * DM];
__device__ float g_v_hi[MROWS * DM], g_v_lo[MROWS * DM];
__device__ float g_Wq_hi[DM * DM], g_Wq_lo[DM * DM];
__device__ float g_Wk_hi[DM * DM], g_Wk_lo[DM * DM];
__device__ float g_Wv_hi[DM * DM], g_Wv_lo[DM * DM];
__device__ float g_Wo_hi[DM * DM], g_Wo_lo[DM * DM];
__device__ float g_qh_hi[MROWS * DM], g_qh_lo[MROWS * DM];
__device__ float g_kh_hi[MROWS * DM], g_kh_lo[MROWS * DM];
__device__ float g_vh_raw[MROWS * DM];
__device__ float g_att_hi[MROWS * DM], g_att_lo[MROWS * DM];

// ---------------- tf32 helpers ----------------
__device__ __forceinline__ unsigned f2tf32(float x) {
    unsigned r;
    asm("cvt.rna.tf32.f32 %0, %1;" : "=r"(r) : "f"(x));
    return r;
}
__device__ __forceinline__ float tf32f(float x) {
    return __uint_as_float(f2tf32(x));
}
__device__ __forceinline__ void splitf(float x, float& h, float& l) {
    h = tf32f(x);
    l = __uint_as_float(f2tf32(x - h));
}
__device__ __forceinline__ void splitu(float x, unsigned& h, unsigned& l) {
    float hf = tf32f(x);
    h = __float_as_uint(hf);
    l = f2tf32(x - hf);
}
__device__ __forceinline__ void mma_tf32(
    float& c0, float& c1, float& c2, float& c3,
    unsigned a0, unsigned a1, unsigned a2, unsigned a3,
    unsigned b0, unsigned b1)
{
    asm volatile(
        "mma.sync.aligned.m16n8k8.row.col.f32.tf32.tf32.f32 "
        "{%0,%1,%2,%3}, {%4,%5,%6,%7}, {%8,%9}, {%0,%1,%2,%3};"
        : "+f"(c0), "+f"(c1), "+f"(c2), "+f"(c3)
        : "r"(a0), "r"(a1), "r"(a2), "r"(a3), "r"(b0), "r"(b1));
}

// ---------------- cp.async helpers ----------------
__device__ __forceinline__ void cp_async16(void* smem_ptr, const void* gptr) {
    unsigned saddr = (unsigned)__cvta_generic_to_shared(smem_ptr);
    asm volatile("cp.async.cg.shared.global [%0], [%1], 16;\n"
                 :: "r"(saddr), "l"(gptr));
}
__device__ __forceinline__ void cp_commit() {
    asm volatile("cp.async.commit_group;\n");
}
template<int N> __device__ __forceinline__ void cp_wait() {
    asm volatile("cp.async.wait_group %0;\n" :: "n"(N));
}

// ---------------- batched split pre-pass ----------------
struct SplitEnt { const float* s; float* h; float* l; int n4; };
struct SplitBatch { SplitEnt e[7]; };

__global__ __launch_bounds__(256) void split7(SplitBatch sb) {
    const SplitEnt& e = sb.e[blockIdx.z];
    int i = blockIdx.x * blockDim.x + threadIdx.x;
    if (i >= e.n4) return;
    float4 x = ((const float4*)e.s)[i];
    float4 h4, l4;
    splitf(x.x, h4.x, l4.x); splitf(x.y, h4.y, l4.y);
    splitf(x.z, h4.z, l4.z); splitf(x.w, h4.w, l4.w);
    ((float4*)e.h)[i] = h4;
    ((float4*)e.l)[i] = l4;
}

// ---------------- 3xTF32 GEMM, pre-split operands, batched, 256 thr ----------------
// C = A * B. 128x128x32 CTA tile, 256 threads = 8 warps (2m x 4n), warp tile 64x32.
// Per-entry ws: 1 -> write C hi/lo planes; 0 -> write raw fp32 to C0.
#define GBM 128
#define GBN 128
#define GBK 32
#define AS_STR 36
#define BS_STR 136
#define A_TILE (GBM * AS_STR)
#define B_TILE (GBK * BS_STR)
#define STAGE_F (2 * (A_TILE + B_TILE))
#define GEMM_SMEM (2 * STAGE_F * 4)          // 143360 B

struct GemmEnt { const float *Ah, *Al, *Bh, *Bl; float *C0, *C1; int ws; };
struct GemmBatch { GemmEnt e[3]; };

__global__ __launch_bounds__(256) void gemm_ps(GemmBatch gb, int M, int N, int K)
{
    extern __shared__ float smg[];
    const GemmEnt& P = gb.e[blockIdx.z];

    int tid  = threadIdx.x;
    int lane = tid & 31;
    int warp = tid >> 5;
    int wm = warp & 1;
    int wn = warp >> 1;
    int g  = lane >> 2;
    int tg = lane & 3;
    int rowBase = blockIdx.y * GBM;
    int colBase = blockIdx.x * GBN;

    auto load_tile = [&](int k0, int s) {
        float* AsH = smg + s * STAGE_F;
        float* AsL = AsH + A_TILE;
        float* BsH = AsL + A_TILE;
        float* BsL = BsH + B_TILE;
#pragma unroll
        for (int it = 0; it < 4; it++) {
            int idx = tid + it * 256;           // 0..1023
            int ar = idx >> 3, ac4 = idx & 7;   // A: 128 x 8 float4
            size_t ga = (size_t)(rowBase + ar) * K + k0 + ac4 * 4;
            cp_async16(&AsH[ar * AS_STR + ac4 * 4], P.Ah + ga);
            cp_async16(&AsL[ar * AS_STR + ac4 * 4], P.Al + ga);
            int br = idx >> 5, bc4 = idx & 31;  // B: 32 x 32 float4
            size_t gbo = (size_t)(k0 + br) * N + colBase + bc4 * 4;
            cp_async16(&BsH[br * BS_STR + bc4 * 4], P.Bh + gbo);
            cp_async16(&BsL[br * BS_STR + bc4 * 4], P.Bl + gbo);
        }
    };

    float acc[4][4][4];
#pragma unroll
    for (int mt = 0; mt < 4; mt++)
#pragma unroll
        for (int nt = 0; nt < 4; nt++)
#pragma unroll
            for (int i = 0; i < 4; i++) acc[mt][nt][i] = 0.f;

    int NT = K / GBK;
    load_tile(0, 0);
    cp_commit();

    for (int t = 0; t < NT; t++) {
        if (t + 1 < NT) load_tile((t + 1) * GBK, (t + 1) & 1);
        cp_commit();
        cp_wait<1>();
        __syncthreads();

        const float* AsH = smg + (t & 1) * STAGE_F;
        const float* AsL = AsH + A_TILE;
        const float* BsH = AsL + A_TILE;
        const float* BsL = BsH + B_TILE;

#pragma unroll
        for (int ks = 0; ks < 4; ks++) {
            int kk = ks * 8 + tg;
            unsigned afH[4][4], afL[4][4];
#pragma unroll
            for (int mt = 0; mt < 4; mt++) {
                int m = wm * 64 + mt * 16 + g;
                afH[mt][0] = __float_as_uint(AsH[m * AS_STR + kk]);
                afH[mt][1] = __float_as_uint(AsH[(m + 8) * AS_STR + kk]);
                afH[mt][2] = __float_as_uint(AsH[m * AS_STR + kk + 4]);
                afH[mt][3] = __float_as_uint(AsH[(m + 8) * AS_STR + kk + 4]);
                afL[mt][0] = __float_as_uint(AsL[m * AS_STR + kk]);
                afL[mt][1] = __float_as_uint(AsL[(m + 8) * AS_STR + kk]);
                afL[mt][2] = __float_as_uint(AsL[m * AS_STR + kk + 4]);
                afL[mt][3] = __float_as_uint(AsL[(m + 8) * AS_STR + kk + 4]);
            }
            unsigned bfH[4][2], bfL[4][2];
#pragma unroll
            for (int nt = 0; nt < 4; nt++) {
                int n = wn * 32 + nt * 8 + g;
                bfH[nt][0] = __float_as_uint(BsH[kk * BS_STR + n]);
                bfH[nt][1] = __float_as_uint(BsH[(kk + 4) * BS_STR + n]);
                bfL[nt][0] = __float_as_uint(BsL[kk * BS_STR + n]);
                bfL[nt][1] = __float_as_uint(BsL[(kk + 4) * BS_STR + n]);
            }
#pragma unroll
            for (int mt = 0; mt < 4; mt++)
#pragma unroll
                for (int nt = 0; nt < 4; nt++) {
                    float* c = acc[mt][nt];
                    mma_tf32(c[0], c[1], c[2], c[3],
                             afH[mt][0], afH[mt][1], afH[mt][2], afH[mt][3],
                             bfL[nt][0], bfL[nt][1]);
                    mma_tf32(c[0], c[1], c[2], c[3],
                             afL[mt][0], afL[mt][1], afL[mt][2], afL[mt][3],
                             bfH[nt][0], bfH[nt][1]);
                    mma_tf32(c[0], c[1], c[2], c[3],
                             afH[mt][0], afH[mt][1], afH[mt][2], afH[mt][3],
                             bfH[nt][0], bfH[nt][1]);
                }
        }
        __syncthreads();
    }

#pragma unroll
    for (int mt = 0; mt < 4; mt++) {
#pragma unroll
        for (int nt = 0; nt < 4; nt++) {
            int r0 = rowBase + wm * 64 + mt * 16 + g;
            int cc = colBase + wn * 32 + nt * 8 + 2 * tg;
            float* c = acc[mt][nt];
            if (P.ws) {
                float h0, l0, h1, l1;
                splitf(c[0], h0, l0); splitf(c[1], h1, l1);
                *(float2*)(P.C0 + (size_t)r0 * N + cc) = make_float2(h0, h1);
                *(float2*)(P.C1 + (size_t)r0 * N + cc) = make_float2(l0, l1);
                splitf(c[2], h0, l0); splitf(c[3], h1, l1);
                *(float2*)(P.C0 + (size_t)(r0 + 8) * N + cc) = make_float2(h0, h1);
                *(float2*)(P.C1 + (size_t)(r0 + 8) * N + cc) = make_float2(l0, l1);
            } else {
                *(float2*)(P.C0 + (size_t)r0 * N + cc)       = make_float2(c[0], c[1]);
                *(float2*)(P.C0 + (size_t)(r0 + 8) * N + cc) = make_float2(c[2], c[3]);
            }
        }
    }
}

// ---------------- 3xTF32 flash attention (causal) ----------------
// CTA per (b, h, 64-row q tile). 128 threads = 4 warps, warp owns 16 q rows.
// K staged pre-split (hi/lo planes); V staged RAW and split in PV loop.
// Smem 106.5 KB -> 2 CTAs/SM. P via shfl. Epilogue writes att pre-split.
// Reference quirk: softmax FIRST, then /sqrt(DH)=8.
#define TQ 64
#define KS_STR 68
#define VS_STR 72
#define K_TILE (TQ * KS_STR)                 // 4352
#define V_TILE (TQ * VS_STR)                 // 4608
#define AST_F (2 * K_TILE + V_TILE)          // 13312 floats per stage
#define ATTN_SMEM (2 * AST_F * 4)            // 106496 B

__global__ __launch_bounds__(128) void attn_ps(
    const float* __restrict__ qhH, const float* __restrict__ qhL,
    const float* __restrict__ khH, const float* __restrict__ khL,
    const float* __restrict__ vhR,
    float* __restrict__ attH, float* __restrict__ attL)
{
    extern __shared__ float sm[];

    int bh = blockIdx.y;
    int b = bh >> 4;
    int h = bh & 15;
    int qt = (L_ / TQ - 1) - blockIdx.x;     // heavy tiles first
    int q0 = qt * TQ;

    int tid  = threadIdx.x;
    int lane = tid & 31;
    int warp = tid >> 5;
    int g  = lane >> 2;
    int tg = lane & 3;

    const size_t base = (size_t)b * L_ * DM + (size_t)h * DH;
    int r0 = q0 + warp * 16 + g;

    auto load_kv = [&](int k0, int s) {
        float* KsH = sm + s * AST_F;
        float* KsL = KsH + K_TILE;
        float* Vs  = KsL + K_TILE;
#pragma unroll
        for (int it = 0; it < 8; it++) {
            int idx = tid + it * 128;        // 0..1023
            int row = idx >> 4, c4 = idx & 15;
            size_t go = base + (size_t)(k0 + row) * DM + c4 * 4;
            cp_async16(&KsH[row * KS_STR + c4 * 4], khH + go);
            cp_async16(&KsL[row * KS_STR + c4 * 4], khL + go);
            cp_async16(&Vs[row * VS_STR + c4 * 4],  vhR + go);
        }
    };

    // Q fragments (hi/lo) straight from pre-split planes
    unsigned qaH[8][4], qaL[8][4];
#pragma unroll
    for (int kd = 0; kd < 8; kd++) {
        int c = kd * 8 + tg;
        size_t i0 = base + (size_t)r0 * DM + c;
        size_t i1 = base + (size_t)(r0 + 8) * DM + c;
        qaH[kd][0] = __float_as_uint(qhH[i0]);
        qaH[kd][1] = __float_as_uint(qhH[i1]);
        qaH[kd][2] = __float_as_uint(qhH[i0 + 4]);
        qaH[kd][3] = __float_as_uint(qhH[i1 + 4]);
        qaL[kd][0] = __float_as_uint(qhL[i0]);
        qaL[kd][1] = __float_as_uint(qhL[i1]);
        qaL[kd][2] = __float_as_uint(qhL[i0 + 4]);
        qaL[kd][3] = __float_as_uint(qhL[i1 + 4]);
    }

    float o[8][4];
#pragma unroll
    for (int nd = 0; nd < 8; nd++)
#pragma unroll
        for (int i = 0; i < 4; i++) o[nd][i] = 0.f;
    float m0 = -1e30f, m1 = -1e30f, l0s = 0.f, l1s = 0.f;

    int ntiles = qt + 1;
    load_kv(0, 0);
    cp_commit();

    for (int t = 0; t < ntiles; t++) {
        if (t + 1 < ntiles) load_kv((t + 1) * TQ, (t + 1) & 1);
        cp_commit();
        cp_wait<1>();
        __syncthreads();

        const float* KsH = sm + (t & 1) * AST_F;
        const float* KsL = KsH + K_TILE;
        const float* Vs  = KsL + K_TILE;
        int k0 = t * TQ;

        // scores: 16 x 64 per warp (K pre-split, no ALU here)
        float s[8][4];
#pragma unroll
        for (int nt = 0; nt < 8; nt++)
#pragma unroll
            for (int i = 0; i < 4; i++) s[nt][i] = 0.f;

#pragma unroll
        for (int kd = 0; kd < 8; kd++) {
            int kk = kd * 8 + tg;
#pragma unroll
            for (int nt = 0; nt < 8; nt++) {
                int nrow = nt * 8 + g;
                unsigned bH0 = __float_as_uint(KsH[nrow * KS_STR + kk]);
                unsigned bH1 = __float_as_uint(KsH[nrow * KS_STR + kk + 4]);
                unsigned bL0 = __float_as_uint(KsL[nrow * KS_STR + kk]);
                unsigned bL1 = __float_as_uint(KsL[nrow * KS_STR + kk + 4]);
                float* c = s[nt];
                mma_tf32(c[0], c[1], c[2], c[3],
                         qaH[kd][0], qaH[kd][1], qaH[kd][2], qaH[kd][3], bL0, bL1);
                mma_tf32(c[0], c[1], c[2], c[3],
                         qaL[kd][0], qaL[kd][1], qaL[kd][2], qaL[kd][3], bH0, bH1);
                mma_tf32(c[0], c[1], c[2], c[3],
                         qaH[kd][0], qaH[kd][1], qaH[kd][2], qaH[kd][3], bH0, bH1);
            }
        }

        // causal mask (only the diagonal tile)
        if (t == ntiles - 1) {
#pragma unroll
            for (int nt = 0; nt < 8; nt++) {
                int col = k0 + nt * 8 + 2 * tg;
                if (col     > r0)     s[nt][0] = -1e9f;
                if (col + 1 > r0)     s[nt][1] = -1e9f;
                if (col     > r0 + 8) s[nt][2] = -1e9f;
                if (col + 1 > r0 + 8) s[nt][3] = -1e9f;
            }
        }

        // online softmax (2 rows per thread)
        float mx0 = -1e30f, mx1 = -1e30f;
#pragma unroll
        for (int nt = 0; nt < 8; nt++) {
            mx0 = fmaxf(mx0, fmaxf(s[nt][0], s[nt][1]));
            mx1 = fmaxf(mx1, fmaxf(s[nt][2], s[nt][3]));
        }
        mx0 = fmaxf(mx0, __shfl_xor_sync(0xffffffffu, mx0, 1));
        mx0 = fmaxf(mx0, __shfl_xor_sync(0xffffffffu, mx0, 2));
        mx1 = fmaxf(mx1, __shfl_xor_sync(0xffffffffu, mx1, 1));
        mx1 = fmaxf(mx1, __shfl_xor_sync(0xffffffffu, mx1, 2));

        float mn0 = fmaxf(m0, mx0), mn1 = fmaxf(m1, mx1);
        float cr0 = __expf(m0 - mn0), cr1 = __expf(m1 - mn1);
        float sum0 = 0.f, sum1 = 0.f;
#pragma unroll
        for (int nt = 0; nt < 8; nt++) {
            s[nt][0] = __expf(s[nt][0] - mn0);
            s[nt][1] = __expf(s[nt][1] - mn0);
            s[nt][2] = __expf(s[nt][2] - mn1);
            s[nt][3] = __expf(s[nt][3] - mn1);
            sum0 += s[nt][0] + s[nt][1];
            sum1 += s[nt][2] + s[nt][3];
        }
        sum0 += __shfl_xor_sync(0xffffffffu, sum0, 1);
        sum0 += __shfl_xor_sync(0xffffffffu, sum0, 2);
        sum1 += __shfl_xor_sync(0xffffffffu, sum1, 1);
        sum1 += __shfl_xor_sync(0xffffffffu, sum1, 2);
        l0s = l0s * cr0 + sum0;
        l1s = l1s * cr1 + sum1;
        m0 = mn0; m1 = mn1;

#pragma unroll
        for (int nd = 0; nd < 8; nd++) {
            o[nd][0] *= cr0; o[nd][1] *= cr0;
            o[nd][2] *= cr1; o[nd][3] *= cr1;
        }

        // PV: P(16x64) x V(64x64). Accum -> A-frag via shfl; V split in-loop.
        int lq = lane & ~3;
        int srcA = lq + (tg >> 1);
        int srcB = srcA + 2;
        bool odd = (tg & 1);
#pragma unroll
        for (int ks = 0; ks < 8; ks++) {
            float w00 = __shfl_sync(0xffffffffu, s[ks][0], srcA);
            float w01 = __shfl_sync(0xffffffffu, s[ks][1], srcA);
            float w02 = __shfl_sync(0xffffffffu, s[ks][2], srcA);
            float w03 = __shfl_sync(0xffffffffu, s[ks][3], srcA);
            float w10 = __shfl_sync(0xffffffffu, s[ks][0], srcB);
            float w11 = __shfl_sync(0xffffffffu, s[ks][1], srcB);
            float w12 = __shfl_sync(0xffffffffu, s[ks][2], srcB);
            float w13 = __shfl_sync(0xffffffffu, s[ks][3], srcB);
            float pa0f = odd ? w01 : w00;
            float pa1f = odd ? w03 : w02;
            float pa2f = odd ? w11 : w10;
            float pa3f = odd ? w13 : w12;
            unsigned pH0, pL0, pH1, pL1, pH2, pL2, pH3, pL3;
            splitu(pa0f, pH0, pL0);
            splitu(pa1f, pH1, pL1);
            splitu(pa2f, pH2, pL2);
            splitu(pa3f, pH3, pL3);

            int kk = ks * 8 + tg;
#pragma unroll
            for (int nd = 0; nd < 8; nd++) {
                unsigned vH0, vL0, vH1, vL1;
                splitu(Vs[kk * VS_STR + nd * 8 + g],       vH0, vL0);
                splitu(Vs[(kk + 4) * VS_STR + nd * 8 + g], vH1, vL1);
                float* c = o[nd];
                mma_tf32(c[0], c[1], c[2], c[3], pH0, pH1, pH2, pH3, vL0, vL1);
                mma_tf32(c[0], c[1], c[2], c[3], pL0, pL1, pL2, pL3, vH0, vH1);
                mma_tf32(c[0], c[1], c[2], c[3], pH0, pH1, pH2, pH3, vH0, vH1);
            }
        }
        __syncthreads();
    }

    // softmax-then-scale quirk: divide by l AND by sqrt(DH)=8; write pre-split
    float inv0 = 1.f / (l0s * 8.f);
    float inv1 = 1.f / (l1s * 8.f);
#pragma unroll
    for (int nd = 0; nd < 8; nd++) {
        int cc = nd * 8 + 2 * tg;
        size_t i0 = base + (size_t)r0 * DM + cc;
        size_t i1 = base + (size_t)(r0 + 8) * DM + cc;
        float h0, l0, h1, l1;
        splitf(o[nd][0] * inv0, h0, l0); splitf(o[nd][1] * inv0, h1, l1);
        *(float2*)(attH + i0) = make_float2(h0, h1);
        *(float2*)(attL + i0) = make_float2(l0, l1);
        splitf(o[nd][2] * inv1, h0, l0); splitf(o[nd][3] * inv1, h1, l1);
        *(float2*)(attH + i1) = make_float2(h0, h1);
        *(float2*)(attL + i1) = make_float2(l0, l1);
    }
}

// ---------------- launch ----------------
extern "C" void kernel_launch(void* const* d_in, const int* in_sizes, int n_in,
                              void* d_out, int out_size)
{
    const float* q  = (const float*)d_in[0];
    const float* k  = (const float*)d_in[1];
    const float* v  = (const float*)d_in[2];
    // d_in[3] is the causal mask -> handled analytically
    const float* Wq = (const float*)d_in[4];
    const float* Wk = (const float*)d_in[5];
    const float* Wv = (const float*)d_in[6];
    const float* Wo = (const float*)d_in[7];
    float* out = (float*)d_out;

    auto ga = [](const void* sym) {
        void* p; cudaGetSymbolAddress(&p, sym); return (float*)p;
    };
    float *qH = ga(g_q_hi), *qL = ga(g_q_lo);
    float *kH = ga(g_k_hi), *kL = ga(g_k_lo);
    float *vH = ga(g_v_hi), *vL = ga(g_v_lo);
    float *WqH = ga(g_Wq_hi), *WqL = ga(g_Wq_lo);
    float *WkH = ga(g_Wk_hi), *WkL = ga(g_Wk_lo);
    float *WvH = ga(g_Wv_hi), *WvL = ga(g_Wv_lo);
    float *WoH = ga(g_Wo_hi), *WoL = ga(g_Wo_lo);
    float *qhH = ga(g_qh_hi), *qhL = ga(g_qh_lo);
    float *khH = ga(g_kh_hi), *khL = ga(g_kh_lo);
    float *vhR = ga(g_vh_raw);
    float *attH = ga(g_att_hi), *attL = ga(g_att_lo);

    static int smem_set = 0;
    if (!smem_set) {
        cudaFuncSetAttribute(gemm_ps, cudaFuncAttributeMaxDynamicSharedMemorySize, GEMM_SMEM);
        cudaFuncSetAttribute(attn_ps, cudaFuncAttributeMaxDynamicSharedMemorySize, ATTN_SMEM);
        smem_set = 1;
    }

    // 1. batched split pre-pass
    SplitBatch sb;
    int n4in = MROWS * DM / 4;
    int n4w  = DM * DM / 4;
    sb.e[0] = {q,  qH,  qL,  n4in};
    sb.e[1] = {k,  kH,  kL,  n4in};
    sb.e[2] = {v,  vH,  vL,  n4in};
    sb.e[3] = {Wq, WqH, WqL, n4w};
    sb.e[4] = {Wk, WkH, WkL, n4w};
    sb.e[5] = {Wv, WvH, WvL, n4w};
    sb.e[6] = {Wo, WoH, WoL, n4w};
    split7<<<dim3(n4in / 256, 1, 7), 256>>>(sb);

    // 2. three projection GEMMs, one batched launch
    //    q,k -> split planes; v -> raw (attention splits V in-loop)
    GemmBatch gp;
    gp.e[0] = {qH, qL, WqH, WqL, qhH, qhL, 1};
    gp.e[1] = {kH, kL, WkH, WkL, khH, khL, 1};
    gp.e[2] = {vH, vL, WvH, WvL, vhR, nullptr, 0};
    gemm_ps<<<dim3(DM / GBN, MROWS / GBM, 3), 256, GEMM_SMEM>>>(gp, MROWS, DM, DM);

    // 3. attention (106.5 KB smem -> 2 CTAs/SM)
    attn_ps<<<dim3(L_ / TQ, B_ * H_), 128, ATTN_SMEM>>>(
        qhH, qhL, khH, khL, vhR, attH, attL);

    // 4. output GEMM, raw fp32 result
    GemmBatch go;
    go.e[0] = {attH, attL, WoH, WoL, out, nullptr, 0};
    go.e[1] = go.e[0];
    go.e[2] = go.e[0];
    gemm_ps<<<dim3(DM / GBN, MROWS / GBM, 1), 256, GEMM_SMEM>>>(go, MROWS, DM, DM);
}

// round 14
// speedup vs baseline: 1.0815x; 1.0310x over previous
#include <cuda_runtime.h>
#include <cstddef>
#include <cstdint>

// Problem constants
#define B_ 2
#define L_ 2048
#define DM 1024
#define H_ 16
#define DH 64
#define MROWS (B_ * L_)   // 4096

// ---------------- scratch (no allocation allowed) ----------------
__device__ float g_q_hi[MROWS * DM], g_q_lo[MROWS * DM];
__device__ float g_k_hi[MROWS * DM], g_k_lo[MROWS * DM];
__device__ float g_v_hi[MROWS * DM], g_v_lo[MROWS * DM];
__device__ float g_Wq_hi[DM * DM], g_Wq_lo[DM * DM];
__device__ float g_Wk_hi[DM * DM], g_Wk_lo[DM * DM];
__device__ float g_Wv_hi[DM * DM], g_Wv_lo[DM * DM];
__device__ float g_Wo_hi[DM * DM], g_Wo_lo[DM * DM];
__device__ float g_qh_hi[MROWS * DM], g_qh_lo[MROWS * DM];
__device__ float g_kh_hi[MROWS * DM], g_kh_lo[MROWS * DM];
__device__ float g_vh_hi[MROWS * DM], g_vh_lo[MROWS * DM];
__device__ float g_att_hi[MROWS * DM], g_att_lo[MROWS * DM];

// ---------------- tf32 helpers ----------------
__device__ __forceinline__ unsigned f2tf32(float x) {
    unsigned r;
    asm("cvt.rna.tf32.f32 %0, %1;" : "=r"(r) : "f"(x));
    return r;
}
__device__ __forceinline__ float tf32f(float x) {
    return __uint_as_float(f2tf32(x));
}
__device__ __forceinline__ void splitf(float x, float& h, float& l) {
    h = tf32f(x);
    l = __uint_as_float(f2tf32(x - h));
}
__device__ __forceinline__ void splitu(float x, unsigned& h, unsigned& l) {
    float hf = tf32f(x);
    h = __float_as_uint(hf);
    l = f2tf32(x - hf);
}
__device__ __forceinline__ void mma_tf32(
    float& c0, float& c1, float& c2, float& c3,
    unsigned a0, unsigned a1, unsigned a2, unsigned a3,
    unsigned b0, unsigned b1)
{
    asm volatile(
        "mma.sync.aligned.m16n8k8.row.col.f32.tf32.tf32.f32 "
        "{%0,%1,%2,%3}, {%4,%5,%6,%7}, {%8,%9}, {%0,%1,%2,%3};"
        : "+f"(c0), "+f"(c1), "+f"(c2), "+f"(c3)
        : "r"(a0), "r"(a1), "r"(a2), "r"(a3), "r"(b0), "r"(b1));
}

// ---------------- cp.async helpers ----------------
__device__ __forceinline__ void cp_async16(void* smem_ptr, const void* gptr) {
    unsigned saddr = (unsigned)__cvta_generic_to_shared(smem_ptr);
    asm volatile("cp.async.cg.shared.global [%0], [%1], 16;\n"
                 :: "r"(saddr), "l"(gptr));
}
__device__ __forceinline__ void cp_commit() {
    asm volatile("cp.async.commit_group;\n");
}
template<int N> __device__ __forceinline__ void cp_wait() {
    asm volatile("cp.async.wait_group %0;\n" :: "n"(N));
}

// ---------------- batched split pre-pass ----------------
struct SplitEnt { const float* s; float* h; float* l; int n4; };
struct SplitBatch { SplitEnt e[7]; };

__global__ __launch_bounds__(256) void split7(SplitBatch sb) {
    const SplitEnt& e = sb.e[blockIdx.z];
    int i = blockIdx.x * blockDim.x + threadIdx.x;
    if (i >= e.n4) return;
    float4 x = ((const float4*)e.s)[i];
    float4 h4, l4;
    splitf(x.x, h4.x, l4.x); splitf(x.y, h4.y, l4.y);
    splitf(x.z, h4.z, l4.z); splitf(x.w, h4.w, l4.w);
    ((float4*)e.h)[i] = h4;
    ((float4*)e.l)[i] = l4;
}

// ---------------- 3xTF32 GEMM, pre-split operands, batched, 256 thr ----------------
// C = A * B. 128x128x32 CTA tile, 256 threads = 8 warps (2m x 4n), warp tile 64x32.
// Per-entry ws: 1 -> write C hi/lo planes; 0 -> write raw fp32 to C0.
#define GBM 128
#define GBN 128
#define GBK 32
#define AS_STR 36
#define BS_STR 136
#define A_TILE (GBM * AS_STR)
#define B_TILE (GBK * BS_STR)
#define STAGE_F (2 * (A_TILE + B_TILE))
#define GEMM_SMEM (2 * STAGE_F * 4)          // 143360 B

struct GemmEnt { const float *Ah, *Al, *Bh, *Bl; float *C0, *C1; int ws; };
struct GemmBatch { GemmEnt e[3]; };

__global__ __launch_bounds__(256) void gemm_ps(GemmBatch gb, int M, int N, int K)
{
    extern __shared__ float smg[];
    const GemmEnt& P = gb.e[blockIdx.z];

    int tid  = threadIdx.x;
    int lane = tid & 31;
    int warp = tid >> 5;
    int wm = warp & 1;
    int wn = warp >> 1;
    int g  = lane >> 2;
    int tg = lane & 3;
    int rowBase = blockIdx.y * GBM;
    int colBase = blockIdx.x * GBN;

    auto load_tile = [&](int k0, int s) {
        float* AsH = smg + s * STAGE_F;
        float* AsL = AsH + A_TILE;
        float* BsH = AsL + A_TILE;
        float* BsL = BsH + B_TILE;
#pragma unroll
        for (int it = 0; it < 4; it++) {
            int idx = tid + it * 256;           // 0..1023
            int ar = idx >> 3, ac4 = idx & 7;   // A: 128 x 8 float4
            size_t ga = (size_t)(rowBase + ar) * K + k0 + ac4 * 4;
            cp_async16(&AsH[ar * AS_STR + ac4 * 4], P.Ah + ga);
            cp_async16(&AsL[ar * AS_STR + ac4 * 4], P.Al + ga);
            int br = idx >> 5, bc4 = idx & 31;  // B: 32 x 32 float4
            size_t gbo = (size_t)(k0 + br) * N + colBase + bc4 * 4;
            cp_async16(&BsH[br * BS_STR + bc4 * 4], P.Bh + gbo);
            cp_async16(&BsL[br * BS_STR + bc4 * 4], P.Bl + gbo);
        }
    };

    float acc[4][4][4];
#pragma unroll
    for (int mt = 0; mt < 4; mt++)
#pragma unroll
        for (int nt = 0; nt < 4; nt++)
#pragma unroll
            for (int i = 0; i < 4; i++) acc[mt][nt][i] = 0.f;

    int NT = K / GBK;
    load_tile(0, 0);
    cp_commit();

    for (int t = 0; t < NT; t++) {
        if (t + 1 < NT) load_tile((t + 1) * GBK, (t + 1) & 1);
        cp_commit();
        cp_wait<1>();
        __syncthreads();

        const float* AsH = smg + (t & 1) * STAGE_F;
        const float* AsL = AsH + A_TILE;
        const float* BsH = AsL + A_TILE;
        const float* BsL = BsH + B_TILE;

#pragma unroll
        for (int ks = 0; ks < 4; ks++) {
            int kk = ks * 8 + tg;
            unsigned afH[4][4], afL[4][4];
#pragma unroll
            for (int mt = 0; mt < 4; mt++) {
                int m = wm * 64 + mt * 16 + g;
                afH[mt][0] = __float_as_uint(AsH[m * AS_STR + kk]);
                afH[mt][1] = __float_as_uint(AsH[(m + 8) * AS_STR + kk]);
                afH[mt][2] = __float_as_uint(AsH[m * AS_STR + kk + 4]);
                afH[mt][3] = __float_as_uint(AsH[(m + 8) * AS_STR + kk + 4]);
                afL[mt][0] = __float_as_uint(AsL[m * AS_STR + kk]);
                afL[mt][1] = __float_as_uint(AsL[(m + 8) * AS_STR + kk]);
                afL[mt][2] = __float_as_uint(AsL[m * AS_STR + kk + 4]);
                afL[mt][3] = __float_as_uint(AsL[(m + 8) * AS_STR + kk + 4]);
            }
            unsigned bfH[4][2], bfL[4][2];
#pragma unroll
            for (int nt = 0; nt < 4; nt++) {
                int n = wn * 32 + nt * 8 + g;
                bfH[nt][0] = __float_as_uint(BsH[kk * BS_STR + n]);
                bfH[nt][1] = __float_as_uint(BsH[(kk + 4) * BS_STR + n]);
                bfL[nt][0] = __float_as_uint(BsL[kk * BS_STR + n]);
                bfL[nt][1] = __float_as_uint(BsL[(kk + 4) * BS_STR + n]);
            }
#pragma unroll
            for (int mt = 0; mt < 4; mt++)
#pragma unroll
                for (int nt = 0; nt < 4; nt++) {
                    float* c = acc[mt][nt];
                    mma_tf32(c[0], c[1], c[2], c[3],
                             afH[mt][0], afH[mt][1], afH[mt][2], afH[mt][3],
                             bfL[nt][0], bfL[nt][1]);
                    mma_tf32(c[0], c[1], c[2], c[3],
                             afL[mt][0], afL[mt][1], afL[mt][2], afL[mt][3],
                             bfH[nt][0], bfH[nt][1]);
                    mma_tf32(c[0], c[1], c[2], c[3],
                             afH[mt][0], afH[mt][1], afH[mt][2], afH[mt][3],
                             bfH[nt][0], bfH[nt][1]);
                }
        }
        __syncthreads();
    }

#pragma unroll
    for (int mt = 0; mt < 4; mt++) {
#pragma unroll
        for (int nt = 0; nt < 4; nt++) {
            int r0 = rowBase + wm * 64 + mt * 16 + g;
            int cc = colBase + wn * 32 + nt * 8 + 2 * tg;
            float* c = acc[mt][nt];
            if (P.ws) {
                float h0, l0, h1, l1;
                splitf(c[0], h0, l0); splitf(c[1], h1, l1);
                *(float2*)(P.C0 + (size_t)r0 * N + cc) = make_float2(h0, h1);
                *(float2*)(P.C1 + (size_t)r0 * N + cc) = make_float2(l0, l1);
                splitf(c[2], h0, l0); splitf(c[3], h1, l1);
                *(float2*)(P.C0 + (size_t)(r0 + 8) * N + cc) = make_float2(h0, h1);
                *(float2*)(P.C1 + (size_t)(r0 + 8) * N + cc) = make_float2(l0, l1);
            } else {
                *(float2*)(P.C0 + (size_t)r0 * N + cc)       = make_float2(c[0], c[1]);
                *(float2*)(P.C0 + (size_t)(r0 + 8) * N + cc) = make_float2(c[2], c[3]);
            }
        }
    }
}

// ---------------- 3xTF32 flash attention (causal), TK=32, all presplit ----------------
// CTA per (b, h, 64-row q tile). 128 threads = 4 warps, warp owns 16 q rows.
// K AND V staged as pre-split hi/lo planes; 32-key tiles; double-buffered.
// Stage = 35.8 KB, total smem 71.7 KB -> 3 CTAs/SM. Zero in-loop split ALU
// except P (16 splitu / tile). Reference quirk: softmax FIRST, then /sqrt(DH)=8.
#define TQ 64
#define TK 32
#define KS_STR 68
#define VS_STR 72
#define K_TILE (TK * KS_STR)                 // 2176
#define V_TILE (TK * VS_STR)                 // 2304
#define AST_F (2 * (K_TILE + V_TILE))        // 8960 floats per stage
#define ATTN_SMEM (2 * AST_F * 4)            // 71680 B

__global__ __launch_bounds__(128, 3) void attn_ps(
    const float* __restrict__ qhH, const float* __restrict__ qhL,
    const float* __restrict__ khH, const float* __restrict__ khL,
    const float* __restrict__ vhH, const float* __restrict__ vhL,
    float* __restrict__ attH, float* __restrict__ attL)
{
    extern __shared__ float sm[];

    int bh = blockIdx.y;
    int b = bh >> 4;
    int h = bh & 15;
    int qt = (L_ / TQ - 1) - blockIdx.x;     // heavy tiles first
    int q0 = qt * TQ;

    int tid  = threadIdx.x;
    int lane = tid & 31;
    int warp = tid >> 5;
    int g  = lane >> 2;
    int tg = lane & 3;

    const size_t base = (size_t)b * L_ * DM + (size_t)h * DH;
    int r0 = q0 + warp * 16 + g;

    auto load_kv = [&](int k0, int s) {
        float* KsH = sm + s * AST_F;
        float* KsL = KsH + K_TILE;
        float* VsH = KsL + K_TILE;
        float* VsL = VsH + V_TILE;
#pragma unroll
        for (int it = 0; it < 4; it++) {
            int idx = tid + it * 128;        // 0..511
            int row = idx >> 4, c4 = idx & 15;
            size_t go = base + (size_t)(k0 + row) * DM + c4 * 4;
            cp_async16(&KsH[row * KS_STR + c4 * 4], khH + go);
            cp_async16(&KsL[row * KS_STR + c4 * 4], khL + go);
            cp_async16(&VsH[row * VS_STR + c4 * 4], vhH + go);
            cp_async16(&VsL[row * VS_STR + c4 * 4], vhL + go);
        }
    };

    // Q fragments (hi/lo) straight from pre-split planes
    unsigned qaH[8][4], qaL[8][4];
#pragma unroll
    for (int kd = 0; kd < 8; kd++) {
        int c = kd * 8 + tg;
        size_t i0 = base + (size_t)r0 * DM + c;
        size_t i1 = base + (size_t)(r0 + 8) * DM + c;
        qaH[kd][0] = __float_as_uint(qhH[i0]);
        qaH[kd][1] = __float_as_uint(qhH[i1]);
        qaH[kd][2] = __float_as_uint(qhH[i0 + 4]);
        qaH[kd][3] = __float_as_uint(qhH[i1 + 4]);
        qaL[kd][0] = __float_as_uint(qhL[i0]);
        qaL[kd][1] = __float_as_uint(qhL[i1]);
        qaL[kd][2] = __float_as_uint(qhL[i0 + 4]);
        qaL[kd][3] = __float_as_uint(qhL[i1 + 4]);
    }

    float o[8][4];
#pragma unroll
    for (int nd = 0; nd < 8; nd++)
#pragma unroll
        for (int i = 0; i < 4; i++) o[nd][i] = 0.f;
    float m0 = -1e30f, m1 = -1e30f, l0s = 0.f, l1s = 0.f;

    int ntiles = 2 * qt + 2;                 // keys [0, q0+TQ) in 32-wide tiles
    load_kv(0, 0);
    cp_commit();

    for (int t = 0; t < ntiles; t++) {
        if (t + 1 < ntiles) load_kv((t + 1) * TK, (t + 1) & 1);
        cp_commit();
        cp_wait<1>();
        __syncthreads();

        const float* KsH = sm + (t & 1) * AST_F;
        const float* KsL = KsH + K_TILE;
        const float* VsH = KsL + K_TILE;
        const float* VsL = VsH + V_TILE;
        int k0 = t * TK;

        // scores: 16 x 32 per warp
        float s[4][4];
#pragma unroll
        for (int nt = 0; nt < 4; nt++)
#pragma unroll
            for (int i = 0; i < 4; i++) s[nt][i] = 0.f;

#pragma unroll
        for (int kd = 0; kd < 8; kd++) {
            int kk = kd * 8 + tg;
#pragma unroll
            for (int nt = 0; nt < 4; nt++) {
                int nrow = nt * 8 + g;
                unsigned bH0 = __float_as_uint(KsH[nrow * KS_STR + kk]);
                unsigned bH1 = __float_as_uint(KsH[nrow * KS_STR + kk + 4]);
                unsigned bL0 = __float_as_uint(KsL[nrow * KS_STR + kk]);
                unsigned bL1 = __float_as_uint(KsL[nrow * KS_STR + kk + 4]);
                float* c = s[nt];
                mma_tf32(c[0], c[1], c[2], c[3],
                         qaH[kd][0], qaH[kd][1], qaH[kd][2], qaH[kd][3], bL0, bL1);
                mma_tf32(c[0], c[1], c[2], c[3],
                         qaL[kd][0], qaL[kd][1], qaL[kd][2], qaL[kd][3], bH0, bH1);
                mma_tf32(c[0], c[1], c[2], c[3],
                         qaH[kd][0], qaH[kd][1], qaH[kd][2], qaH[kd][3], bH0, bH1);
            }
        }

        // causal mask: only the last two 32-wide tiles can touch the diagonal
        if (t >= 2 * qt) {
#pragma unroll
            for (int nt = 0; nt < 4; nt++) {
                int col = k0 + nt * 8 + 2 * tg;
                if (col     > r0)     s[nt][0] = -1e9f;
                if (col + 1 > r0)     s[nt][1] = -1e9f;
                if (col     > r0 + 8) s[nt][2] = -1e9f;
                if (col + 1 > r0 + 8) s[nt][3] = -1e9f;
            }
        }

        // online softmax (2 rows per thread)
        float mx0 = -1e30f, mx1 = -1e30f;
#pragma unroll
        for (int nt = 0; nt < 4; nt++) {
            mx0 = fmaxf(mx0, fmaxf(s[nt][0], s[nt][1]));
            mx1 = fmaxf(mx1, fmaxf(s[nt][2], s[nt][3]));
        }
        mx0 = fmaxf(mx0, __shfl_xor_sync(0xffffffffu, mx0, 1));
        mx0 = fmaxf(mx0, __shfl_xor_sync(0xffffffffu, mx0, 2));
        mx1 = fmaxf(mx1, __shfl_xor_sync(0xffffffffu, mx1, 1));
        mx1 = fmaxf(mx1, __shfl_xor_sync(0xffffffffu, mx1, 2));

        float mn0 = fmaxf(m0, mx0), mn1 = fmaxf(m1, mx1);
        float cr0 = __expf(m0 - mn0), cr1 = __expf(m1 - mn1);
        float sum0 = 0.f, sum1 = 0.f;
#pragma unroll
        for (int nt = 0; nt < 4; nt++) {
            s[nt][0] = __expf(s[nt][0] - mn0);
            s[nt][1] = __expf(s[nt][1] - mn0);
            s[nt][2] = __expf(s[nt][2] - mn1);
            s[nt][3] = __expf(s[nt][3] - mn1);
            sum0 += s[nt][0] + s[nt][1];
            sum1 += s[nt][2] + s[nt][3];
        }
        sum0 += __shfl_xor_sync(0xffffffffu, sum0, 1);
        sum0 += __shfl_xor_sync(0xffffffffu, sum0, 2);
        sum1 += __shfl_xor_sync(0xffffffffu, sum1, 1);
        sum1 += __shfl_xor_sync(0xffffffffu, sum1, 2);
        l0s = l0s * cr0 + sum0;
        l1s = l1s * cr1 + sum1;
        m0 = mn0; m1 = mn1;

#pragma unroll
        for (int nd = 0; nd < 8; nd++) {
            o[nd][0] *= cr0; o[nd][1] *= cr0;
            o[nd][2] *= cr1; o[nd][3] *= cr1;
        }

        // PV: P(16x32) x V(32x64). Accum -> A-frag via shfl; V presplit (no ALU).
        int lq = lane & ~3;
        int srcA = lq + (tg >> 1);
        int srcB = srcA + 2;
        bool odd = (tg & 1);
#pragma unroll
        for (int ks = 0; ks < 4; ks++) {
            float w00 = __shfl_sync(0xffffffffu, s[ks][0], srcA);
            float w01 = __shfl_sync(0xffffffffu, s[ks][1], srcA);
            float w02 = __shfl_sync(0xffffffffu, s[ks][2], srcA);
            float w03 = __shfl_sync(0xffffffffu, s[ks][3], srcA);
            float w10 = __shfl_sync(0xffffffffu, s[ks][0], srcB);
            float w11 = __shfl_sync(0xffffffffu, s[ks][1], srcB);
            float w12 = __shfl_sync(0xffffffffu, s[ks][2], srcB);
            float w13 = __shfl_sync(0xffffffffu, s[ks][3], srcB);
            float pa0f = odd ? w01 : w00;
            float pa1f = odd ? w03 : w02;
            float pa2f = odd ? w11 : w10;
            float pa3f = odd ? w13 : w12;
            unsigned pH0, pL0, pH1, pL1, pH2, pL2, pH3, pL3;
            splitu(pa0f, pH0, pL0);
            splitu(pa1f, pH1, pL1);
            splitu(pa2f, pH2, pL2);
            splitu(pa3f, pH3, pL3);

            int kk = ks * 8 + tg;
#pragma unroll
            for (int nd = 0; nd < 8; nd++) {
                unsigned vH0 = __float_as_uint(VsH[kk * VS_STR + nd * 8 + g]);
                unsigned vH1 = __float_as_uint(VsH[(kk + 4) * VS_STR + nd * 8 + g]);
                unsigned vL0 = __float_as_uint(VsL[kk * VS_STR + nd * 8 + g]);
                unsigned vL1 = __float_as_uint(VsL[(kk + 4) * VS_STR + nd * 8 + g]);
                float* c = o[nd];
                mma_tf32(c[0], c[1], c[2], c[3], pH0, pH1, pH2, pH3, vL0, vL1);
                mma_tf32(c[0], c[1], c[2], c[3], pL0, pL1, pL2, pL3, vH0, vH1);
                mma_tf32(c[0], c[1], c[2], c[3], pH0, pH1, pH2, pH3, vH0, vH1);
            }
        }
        __syncthreads();   // smem reads done before next iter's cp.async overwrite
    }

    // softmax-then-scale quirk: divide by l AND by sqrt(DH)=8; write pre-split
    float inv0 = 1.f / (l0s * 8.f);
    float inv1 = 1.f / (l1s * 8.f);
#pragma unroll
    for (int nd = 0; nd < 8; nd++) {
        int cc = nd * 8 + 2 * tg;
        size_t i0 = base + (size_t)r0 * DM + cc;
        size_t i1 = base + (size_t)(r0 + 8) * DM + cc;
        float h0, l0, h1, l1;
        splitf(o[nd][0] * inv0, h0, l0); splitf(o[nd][1] * inv0, h1, l1);
        *(float2*)(attH + i0) = make_float2(h0, h1);
        *(float2*)(attL + i0) = make_float2(l0, l1);
        splitf(o[nd][2] * inv1, h0, l0); splitf(o[nd][3] * inv1, h1, l1);
        *(float2*)(attH + i1) = make_float2(h0, h1);
        *(float2*)(attL + i1) = make_float2(l0, l1);
    }
}

// ---------------- launch ----------------
extern "C" void kernel_launch(void* const* d_in, const int* in_sizes, int n_in,
                              void* d_out, int out_size)
{
    const float* q  = (const float*)d_in[0];
    const float* k  = (const float*)d_in[1];
    const float* v  = (const float*)d_in[2];
    // d_in[3] is the causal mask -> handled analytically
    const float* Wq = (const float*)d_in[4];
    const float* Wk = (const float*)d_in[5];
    const float* Wv = (const float*)d_in[6];
    const float* Wo = (const float*)d_in[7];
    float* out = (float*)d_out;

    auto ga = [](const void* sym) {
        void* p; cudaGetSymbolAddress(&p, sym); return (float*)p;
    };
    float *qH = ga(g_q_hi), *qL = ga(g_q_lo);
    float *kH = ga(g_k_hi), *kL = ga(g_k_lo);
    float *vH = ga(g_v_hi), *vL = ga(g_v_lo);
    float *WqH = ga(g_Wq_hi), *WqL = ga(g_Wq_lo);
    float *WkH = ga(g_Wk_hi), *WkL = ga(g_Wk_lo);
    float *WvH = ga(g_Wv_hi), *WvL = ga(g_Wv_lo);
    float *WoH = ga(g_Wo_hi), *WoL = ga(g_Wo_lo);
    float *qhH = ga(g_qh_hi), *qhL = ga(g_qh_lo);
    float *khH = ga(g_kh_hi), *khL = ga(g_kh_lo);
    float *vhH = ga(g_vh_hi), *vhL = ga(g_vh_lo);
    float *attH = ga(g_att_hi), *attL = ga(g_att_lo);

    static int smem_set = 0;
    if (!smem_set) {
        cudaFuncSetAttribute(gemm_ps, cudaFuncAttributeMaxDynamicSharedMemorySize, GEMM_SMEM);
        cudaFuncSetAttribute(attn_ps, cudaFuncAttributeMaxDynamicSharedMemorySize, ATTN_SMEM);
        smem_set = 1;
    }

    // 1. batched split pre-pass
    SplitBatch sb;
    int n4in = MROWS * DM / 4;
    int n4w  = DM * DM / 4;
    sb.e[0] = {q,  qH,  qL,  n4in};
    sb.e[1] = {k,  kH,  kL,  n4in};
    sb.e[2] = {v,  vH,  vL,  n4in};
    sb.e[3] = {Wq, WqH, WqL, n4w};
    sb.e[4] = {Wk, WkH, WkL, n4w};
    sb.e[5] = {Wv, WvH, WvL, n4w};
    sb.e[6] = {Wo, WoH, WoL, n4w};
    split7<<<dim3(n4in / 256, 1, 7), 256>>>(sb);

    // 2. three projection GEMMs, one batched launch, all split outputs
    GemmBatch gp;
    gp.e[0] = {qH, qL, WqH, WqL, qhH, qhL, 1};
    gp.e[1] = {kH, kL, WkH, WkL, khH, khL, 1};
    gp.e[2] = {vH, vL, WvH, WvL, vhH, vhL, 1};
    gemm_ps<<<dim3(DM / GBN, MROWS / GBM, 3), 256, GEMM_SMEM>>>(gp, MROWS, DM, DM);

    // 3. attention (71.7 KB smem, launch_bounds(128,3) -> up to 3 CTAs/SM)
    attn_ps<<<dim3(L_ / TQ, B_ * H_), 128, ATTN_SMEM>>>(
        qhH, qhL, khH, khL, vhH, vhL, attH, attL);

    // 4. output GEMM, raw fp32 result
    GemmBatch go;
    go.e[0] = {attH, attL, WoH, WoL, out, nullptr, 0};
    go.e[1] = go.e[0];
    go.e[2] = go.e[0];
    gemm_ps<<<dim3(DM / GBN, MROWS / GBM, 1), 256, GEMM_SMEM>>>(go, MROWS, DM, DM);
}

// round 15
// speedup vs baseline: 1.9180x; 1.7735x over previous
#include <cuda_runtime.h>
#include <cuda_bf16.h>
#include <cstddef>
#include <cstdint>

// Problem constants
#define B_ 2
#define L_ 2048
#define DM 1024
#define H_ 16
#define DH 64
#define MROWS (B_ * L_)   // 4096

typedef __nv_bfloat16 bf16;
typedef __nv_bfloat162 bf162;

// ---------------- scratch (no allocation allowed) ----------------
__device__ bf16 g_q_hi[MROWS * DM],  g_q_lo[MROWS * DM];
__device__ bf16 g_k_hi[MROWS * DM],  g_k_lo[MROWS * DM];
__device__ bf16 g_v_hi[MROWS * DM],  g_v_lo[MROWS * DM];
__device__ bf16 g_WqT_hi[DM * DM], g_WqT_lo[DM * DM];
__device__ bf16 g_WkT_hi[DM * DM], g_WkT_lo[DM * DM];
__device__ bf16 g_WvT_hi[DM * DM], g_WvT_lo[DM * DM];
__device__ bf16 g_WoT_hi[DM * DM], g_WoT_lo[DM * DM];
__device__ bf16 g_qh_hi[MROWS * DM], g_qh_lo[MROWS * DM];
__device__ bf16 g_kh_hi[MROWS * DM], g_kh_lo[MROWS * DM];
__device__ float g_vh_raw[MROWS * DM];
__device__ bf16 g_vt_hi[B_ * H_ * DH * L_], g_vt_lo[B_ * H_ * DH * L_];
__device__ bf16 g_att_hi[MROWS * DM], g_att_lo[MROWS * DM];

// ---------------- bf16 helpers ----------------
// pack two fp32 into bf16x2 (even in low half) + lo-residual plane
__device__ __forceinline__ void packsplit2(float e, float o, unsigned& hu, unsigned& lu) {
    bf162 hh = __floats2bfloat162_rn(e, o);
    float2 hf = __bfloat1622float2(hh);
    bf162 ll = __floats2bfloat162_rn(e - hf.x, o - hf.y);
    hu = *reinterpret_cast<unsigned*>(&hh);
    lu = *reinterpret_cast<unsigned*>(&ll);
}
__device__ __forceinline__ void mma_bf16(
    float& c0, float& c1, float& c2, float& c3,
    unsigned a0, unsigned a1, unsigned a2, unsigned a3,
    unsigned b0, unsigned b1)
{
    asm volatile(
        "mma.sync.aligned.m16n8k16.row.col.f32.bf16.bf16.f32 "
        "{%0,%1,%2,%3}, {%4,%5,%6,%7}, {%8,%9}, {%0,%1,%2,%3};"
        : "+f"(c0), "+f"(c1), "+f"(c2), "+f"(c3)
        : "r"(a0), "r"(a1), "r"(a2), "r"(a3), "r"(b0), "r"(b1));
}

// ---------------- cp.async helpers ----------------
__device__ __forceinline__ void cp_async16(void* smem_ptr, const void* gptr) {
    unsigned saddr = (unsigned)__cvta_generic_to_shared(smem_ptr);
    asm volatile("cp.async.cg.shared.global [%0], [%1], 16;\n"
                 :: "r"(saddr), "l"(gptr));
}
__device__ __forceinline__ void cp_commit() {
    asm volatile("cp.async.commit_group;\n");
}
template<int N> __device__ __forceinline__ void cp_wait() {
    asm volatile("cp.async.wait_group %0;\n" :: "n"(N));
}

// ---------------- pre-pass 1: split activations (q,k,v) ----------------
struct SplitEnt { const float* s; bf16* h; bf16* l; };

__global__ __launch_bounds__(256) void split_acts(SplitEnt e0, SplitEnt e1, SplitEnt e2) {
    const SplitEnt& e = (blockIdx.z == 0) ? e0 : (blockIdx.z == 1) ? e1 : e2;
    int i = blockIdx.x * 256 + threadIdx.x;        // float4 index
    float4 x = ((const float4*)e.s)[i];
    bf162 h01 = __floats2bfloat162_rn(x.x, x.y);
    float2 f01 = __bfloat1622float2(h01);
    bf162 l01 = __floats2bfloat162_rn(x.x - f01.x, x.y - f01.y);
    bf162 h23 = __floats2bfloat162_rn(x.z, x.w);
    float2 f23 = __bfloat1622float2(h23);
    bf162 l23 = __floats2bfloat162_rn(x.z - f23.x, x.w - f23.y);
    ((bf162*)e.h)[2 * i]     = h01;
    ((bf162*)e.h)[2 * i + 1] = h23;
    ((bf162*)e.l)[2 * i]     = l01;
    ((bf162*)e.l)[2 * i + 1] = l23;
}

// ---------------- pre-pass 2: transpose+split weights W[k][n] -> Wt[n][k] ----------------
struct WEnt { const float* w; bf16* th; bf16* tl; };
struct WBatch { WEnt e[4]; };

__global__ __launch_bounds__(256) void wtrans(WBatch wb) {
    const WEnt& e = wb.e[blockIdx.z];
    __shared__ float t[32][33];
    int tx = threadIdx.x & 31, ty = threadIdx.x >> 5;
    int n0 = blockIdx.x * 32, k0 = blockIdx.y * 32;
#pragma unroll
    for (int j = 0; j < 4; j++)
        t[ty + 8 * j][tx] = e.w[(size_t)(k0 + ty + 8 * j) * DM + n0 + tx];
    __syncthreads();
#pragma unroll
    for (int j = 0; j < 4; j++) {
        float x = t[tx][ty + 8 * j];
        bf16 h = __float2bfloat16_rn(x);
        bf16 l = __float2bfloat16_rn(x - __bfloat162float(h));
        size_t o = (size_t)(n0 + ty + 8 * j) * DM + k0 + tx;
        e.th[o] = h; e.tl[o] = l;
    }
}

// ---------------- pre-pass 3: transpose+split V: [b,L,h,d] -> [bh,d,L] ----------------
__global__ __launch_bounds__(256) void vtrans(const float* __restrict__ vr,
                                              bf16* __restrict__ th, bf16* __restrict__ tl) {
    __shared__ float t[32][33];
    int tx = threadIdx.x & 31, ty = threadIdx.x >> 5;
    int bh = blockIdx.z;
    int b = bh >> 4, h = bh & 15;
    int l0 = blockIdx.x * 32;
    int d0 = blockIdx.y * 32;
#pragma unroll
    for (int j = 0; j < 4; j++)
        t[ty + 8 * j][tx] = vr[(size_t)(b * L_ + l0 + ty + 8 * j) * DM + h * DH + d0 + tx];
    __syncthreads();
#pragma unroll
    for (int j = 0; j < 4; j++) {
        float x = t[tx][ty + 8 * j];
        bf16 hh = __float2bfloat16_rn(x);
        bf16 ll = __float2bfloat16_rn(x - __bfloat162float(hh));
        size_t o = (size_t)(bh * DH + d0 + ty + 8 * j) * L_ + l0 + tx;
        th[o] = hh; tl[o] = ll;
    }
}

// ---------------- 3xBF16 GEMM: C[M,N] = A[M,K] * B[K,N] ----------------
// A given as hi/lo bf16 planes [M][K]; B given TRANSPOSED as Bt[n][k] hi/lo planes.
// 128x128x32 CTA tile, 256 threads = 8 warps (2m x 4n), warp 64x32, m16n8k16.
// Products: AhBh + AhBl + AlBh.
#define GBM 128
#define GBN 128
#define GBK 32
#define A_STR 40                      // bf16 per row: 32 data + 8 pad (80B, conflict-free)
#define PLANE_E (128 * A_STR)         // 5120 bf16
#define PLANE_W (PLANE_E / 2)         // 2560 words
#define STAGE_E (4 * PLANE_E)         // AH,AL,BH,BL
#define GEMM_SMEM (2 * STAGE_E * 2)   // 81920 B

struct GemmEnt {
    const bf16 *Ah, *Al, *Bh, *Bl;    // Bt planes [n][k]
    bf16 *CbH, *CbL;                  // ws=1: split bf16 outputs
    float *Cf;                        // ws=0: raw fp32 output
    int ws;
};
struct GemmBatch { GemmEnt e[3]; };

__global__ __launch_bounds__(256, 2) void gemm_bf3(GemmBatch gb, int M, int N, int K)
{
    extern __shared__ bf16 smg[];
    const GemmEnt& P = gb.e[blockIdx.z];

    int tid  = threadIdx.x;
    int lane = tid & 31;
    int warp = tid >> 5;
    int wm = warp & 1, wn = warp >> 1;
    int g  = lane >> 2, tg = lane & 3;
    int rowBase = blockIdx.y * GBM;
    int colBase = blockIdx.x * GBN;

    auto load_tile = [&](int k0, int s) {
        bf16* st = smg + s * STAGE_E;
#pragma unroll
        for (int it = 0; it < 8; it++) {
            int idx = tid + it * 256;            // 0..2047 chunks of 16B
            int plane = idx >> 9;                // 0 AH, 1 AL, 2 BH, 3 BL
            int i = idx & 511;
            int row = i >> 2, c = i & 3;
            const bf16* gp = (plane == 0) ? P.Ah : (plane == 1) ? P.Al
                           : (plane == 2) ? P.Bh : P.Bl;
            int gbase = (plane < 2) ? rowBase : colBase;
            cp_async16(st + plane * PLANE_E + row * A_STR + c * 8,
                       gp + (size_t)(gbase + row) * K + k0 + c * 8);
        }
    };

    float acc[4][4][4];
#pragma unroll
    for (int mt = 0; mt < 4; mt++)
#pragma unroll
        for (int nt = 0; nt < 4; nt++)
#pragma unroll
            for (int i = 0; i < 4; i++) acc[mt][nt][i] = 0.f;

    int NT = K / GBK;
    load_tile(0, 0);
    cp_commit();

    for (int t = 0; t < NT; t++) {
        if (t + 1 < NT) load_tile((t + 1) * GBK, (t + 1) & 1);
        cp_commit();
        cp_wait<1>();
        __syncthreads();

        const unsigned* sAH = (const unsigned*)(smg + (t & 1) * STAGE_E);
        const unsigned* sAL = sAH + PLANE_W;
        const unsigned* sBH = sAH + 2 * PLANE_W;
        const unsigned* sBL = sAH + 3 * PLANE_W;

#pragma unroll
        for (int s = 0; s < 2; s++) {            // two k16 steps per 32-K tile
            unsigned afH[4][4], afL[4][4];
#pragma unroll
            for (int mt = 0; mt < 4; mt++) {
                int m = wm * 64 + mt * 16 + g;
                int w0 = m * 20 + s * 8 + tg;    // row stride 20 words
                afH[mt][0] = sAH[w0];       afH[mt][1] = sAH[w0 + 160];
                afH[mt][2] = sAH[w0 + 4];   afH[mt][3] = sAH[w0 + 164];
                afL[mt][0] = sAL[w0];       afL[mt][1] = sAL[w0 + 160];
                afL[mt][2] = sAL[w0 + 4];   afL[mt][3] = sAL[w0 + 164];
            }
            unsigned bfH[4][2], bfL[4][2];
#pragma unroll
            for (int nt = 0; nt < 4; nt++) {
                int n = wn * 32 + nt * 8 + g;
                int w0 = n * 20 + s * 8 + tg;
                bfH[nt][0] = sBH[w0];  bfH[nt][1] = sBH[w0 + 4];
                bfL[nt][0] = sBL[w0];  bfL[nt][1] = sBL[w0 + 4];
            }
#pragma unroll
            for (int mt = 0; mt < 4; mt++)
#pragma unroll
                for (int nt = 0; nt < 4; nt++) {
                    float* c = acc[mt][nt];
                    mma_bf16(c[0], c[1], c[2], c[3],
                             afH[mt][0], afH[mt][1], afH[mt][2], afH[mt][3],
                             bfL[nt][0], bfL[nt][1]);
                    mma_bf16(c[0], c[1], c[2], c[3],
                             afL[mt][0], afL[mt][1], afL[mt][2], afL[mt][3],
                             bfH[nt][0], bfH[nt][1]);
                    mma_bf16(c[0], c[1], c[2], c[3],
                             afH[mt][0], afH[mt][1], afH[mt][2], afH[mt][3],
                             bfH[nt][0], bfH[nt][1]);
                }
        }
        __syncthreads();
    }

#pragma unroll
    for (int mt = 0; mt < 4; mt++) {
#pragma unroll
        for (int nt = 0; nt < 4; nt++) {
            int r0 = rowBase + wm * 64 + mt * 16 + g;
            int cc = colBase + wn * 32 + nt * 8 + 2 * tg;
            float* c = acc[mt][nt];
            if (P.ws) {
                unsigned hu, lu;
                size_t o0 = (size_t)r0 * N + cc;
                size_t o1 = (size_t)(r0 + 8) * N + cc;
                packsplit2(c[0], c[1], hu, lu);
                *(unsigned*)(P.CbH + o0) = hu; *(unsigned*)(P.CbL + o0) = lu;
                packsplit2(c[2], c[3], hu, lu);
                *(unsigned*)(P.CbH + o1) = hu; *(unsigned*)(P.CbL + o1) = lu;
            } else {
                *(float2*)(P.Cf + (size_t)r0 * N + cc)       = make_float2(c[0], c[1]);
                *(float2*)(P.Cf + (size_t)(r0 + 8) * N + cc) = make_float2(c[2], c[3]);
            }
        }
    }
}

// ---------------- 3xBF16 flash attention (causal) ----------------
// CTA per (b, h, 64-row q tile). 128 threads = 4 warps, warp owns 16 q rows.
// K tiles [key][d] hi/lo bf16 planes; V tiles TRANSPOSED [d][key] hi/lo planes.
// P accumulator pairs ARE the bf16 k16 A-frag pairs: no shfl conversion.
// Reference quirk: softmax FIRST, then /sqrt(DH)=8.
#define TQ 64
#define KV_STR_W 36                   // words per row: 32 data + 4 pad (144B)
#define TILE_W (64 * KV_STR_W)        // 2304 words
#define ASTAGE_W (4 * TILE_W)         // Kh,Kl,Vh,Vl = 9216 words
#define ATTN_SMEM (2 * ASTAGE_W * 4)  // 73728 B

__global__ __launch_bounds__(128, 3) void attn_bf3(
    const bf16* __restrict__ qhH, const bf16* __restrict__ qhL,
    const bf16* __restrict__ khH, const bf16* __restrict__ khL,
    const bf16* __restrict__ vtH, const bf16* __restrict__ vtL,
    bf16* __restrict__ attH, bf16* __restrict__ attL)
{
    extern __shared__ unsigned smw[];

    int bh = blockIdx.y;
    int b = bh >> 4;
    int h = bh & 15;
    int qt = (L_ / TQ - 1) - blockIdx.x;     // heavy tiles first
    int q0 = qt * TQ;

    int tid  = threadIdx.x;
    int lane = tid & 31;
    int warp = tid >> 5;
    int g  = lane >> 2;
    int tg = lane & 3;

    size_t bL = (size_t)b * L_;
    int r0 = q0 + warp * 16 + g;

    auto load_kv = [&](int k0, int s) {
        unsigned* st = smw + s * ASTAGE_W;
#pragma unroll
        for (int it = 0; it < 16; it++) {
            int idx = tid + it * 128;        // 0..2047 chunks
            int tensor = idx >> 10;          // 0 = K, 1 = V
            int plane  = (idx >> 9) & 1;     // 0 = hi, 1 = lo
            int i = idx & 511;
            int row = i >> 3, c = i & 7;
            if (tensor == 0) {
                const bf16* gp = plane ? khL : khH;
                cp_async16(st + plane * TILE_W + row * KV_STR_W + c * 4,
                           gp + (bL + k0 + row) * DM + h * DH + c * 8);
            } else {
                const bf16* gp = plane ? vtL : vtH;
                cp_async16(st + (2 + plane) * TILE_W + row * KV_STR_W + c * 4,
                           gp + (size_t)(bh * DH + row) * L_ + k0 + c * 8);
            }
        }
    };

    // Q fragments straight from pre-split planes (packed bf16x2 words)
    unsigned qaH[4][4], qaL[4][4];
    {
        const unsigned* q0H = (const unsigned*)(qhH + (bL + r0) * DM + h * DH);
        const unsigned* q1H = (const unsigned*)(qhH + (bL + r0 + 8) * DM + h * DH);
        const unsigned* q0L = (const unsigned*)(qhL + (bL + r0) * DM + h * DH);
        const unsigned* q1L = (const unsigned*)(qhL + (bL + r0 + 8) * DM + h * DH);
#pragma unroll
        for (int kd = 0; kd < 4; kd++) {
            qaH[kd][0] = q0H[kd * 8 + tg];  qaH[kd][1] = q1H[kd * 8 + tg];
            qaH[kd][2] = q0H[kd * 8 + tg + 4];  qaH[kd][3] = q1H[kd * 8 + tg + 4];
            qaL[kd][0] = q0L[kd * 8 + tg];  qaL[kd][1] = q1L[kd * 8 + tg];
            qaL[kd][2] = q0L[kd * 8 + tg + 4];  qaL[kd][3] = q1L[kd * 8 + tg + 4];
        }
    }

    float o[8][4];
#pragma unroll
    for (int nd = 0; nd < 8; nd++)
#pragma unroll
        for (int i = 0; i < 4; i++) o[nd][i] = 0.f;
    float m0 = -1e30f, m1 = -1e30f, l0s = 0.f, l1s = 0.f;

    int ntiles = qt + 1;
    load_kv(0, 0);
    cp_commit();

    for (int t = 0; t < ntiles; t++) {
        if (t + 1 < ntiles) load_kv((t + 1) * TQ, (t + 1) & 1);
        cp_commit();
        cp_wait<1>();
        __syncthreads();

        const unsigned* KsH = smw + (t & 1) * ASTAGE_W;
        const unsigned* KsL = KsH + TILE_W;
        const unsigned* VsH = KsH + 2 * TILE_W;
        const unsigned* VsL = KsH + 3 * TILE_W;
        int k0 = t * TQ;

        // scores: 16 x 64 per warp, 4 k16 steps x 8 n-tiles
        float s[8][4];
#pragma unroll
        for (int nt = 0; nt < 8; nt++)
#pragma unroll
            for (int i = 0; i < 4; i++) s[nt][i] = 0.f;

#pragma unroll
        for (int kd = 0; kd < 4; kd++) {
#pragma unroll
            for (int nt = 0; nt < 8; nt++) {
                int w = (nt * 8 + g) * KV_STR_W + kd * 8 + tg;
                unsigned bH0 = KsH[w], bH1 = KsH[w + 4];
                unsigned bL0 = KsL[w], bL1 = KsL[w + 4];
                float* c = s[nt];
                mma_bf16(c[0], c[1], c[2], c[3],
                         qaH[kd][0], qaH[kd][1], qaH[kd][2], qaH[kd][3], bL0, bL1);
                mma_bf16(c[0], c[1], c[2], c[3],
                         qaL[kd][0], qaL[kd][1], qaL[kd][2], qaL[kd][3], bH0, bH1);
                mma_bf16(c[0], c[1], c[2], c[3],
                         qaH[kd][0], qaH[kd][1], qaH[kd][2], qaH[kd][3], bH0, bH1);
            }
        }

        // causal mask (only the diagonal tile)
        if (t == ntiles - 1) {
#pragma unroll
            for (int nt = 0; nt < 8; nt++) {
                int col = k0 + nt * 8 + 2 * tg;
                if (col     > r0)     s[nt][0] = -1e9f;
                if (col + 1 > r0)     s[nt][1] = -1e9f;
                if (col     > r0 + 8) s[nt][2] = -1e9f;
                if (col + 1 > r0 + 8) s[nt][3] = -1e9f;
            }
        }

        // online softmax (2 rows per thread)
        float mx0 = -1e30f, mx1 = -1e30f;
#pragma unroll
        for (int nt = 0; nt < 8; nt++) {
            mx0 = fmaxf(mx0, fmaxf(s[nt][0], s[nt][1]));
            mx1 = fmaxf(mx1, fmaxf(s[nt][2], s[nt][3]));
        }
        mx0 = fmaxf(mx0, __shfl_xor_sync(0xffffffffu, mx0, 1));
        mx0 = fmaxf(mx0, __shfl_xor_sync(0xffffffffu, mx0, 2));
        mx1 = fmaxf(mx1, __shfl_xor_sync(0xffffffffu, mx1, 1));
        mx1 = fmaxf(mx1, __shfl_xor_sync(0xffffffffu, mx1, 2));

        float mn0 = fmaxf(m0, mx0), mn1 = fmaxf(m1, mx1);
        float cr0 = __expf(m0 - mn0), cr1 = __expf(m1 - mn1);
        float sum0 = 0.f, sum1 = 0.f;
#pragma unroll
        for (int nt = 0; nt < 8; nt++) {
            s[nt][0] = __expf(s[nt][0] - mn0);
            s[nt][1] = __expf(s[nt][1] - mn0);
            s[nt][2] = __expf(s[nt][2] - mn1);
            s[nt][3] = __expf(s[nt][3] - mn1);
            sum0 += s[nt][0] + s[nt][1];
            sum1 += s[nt][2] + s[nt][3];
        }
        sum0 += __shfl_xor_sync(0xffffffffu, sum0, 1);
        sum0 += __shfl_xor_sync(0xffffffffu, sum0, 2);
        sum1 += __shfl_xor_sync(0xffffffffu, sum1, 1);
        sum1 += __shfl_xor_sync(0xffffffffu, sum1, 2);
        l0s = l0s * cr0 + sum0;
        l1s = l1s * cr1 + sum1;
        m0 = mn0; m1 = mn1;

#pragma unroll
        for (int nd = 0; nd < 8; nd++) {
            o[nd][0] *= cr0; o[nd][1] *= cr0;
            o[nd][2] *= cr1; o[nd][3] *= cr1;
        }

        // PV: accumulator pairs == bf16 A-frag pairs -> pure register packing.
#pragma unroll
        for (int ks = 0; ks < 4; ks++) {
            unsigned pH0, pL0, pH1, pL1, pH2, pL2, pH3, pL3;
            packsplit2(s[2*ks][0],     s[2*ks][1],     pH0, pL0);  // row g,   keys 16ks+2tg..
            packsplit2(s[2*ks][2],     s[2*ks][3],     pH1, pL1);  // row g+8
            packsplit2(s[2*ks+1][0],   s[2*ks+1][1],   pH2, pL2);  // row g,   keys +8
            packsplit2(s[2*ks+1][2],   s[2*ks+1][3],   pH3, pL3);  // row g+8
#pragma unroll
            for (int nd = 0; nd < 8; nd++) {
                int w = (nd * 8 + g) * KV_STR_W + ks * 8 + tg;
                unsigned vH0 = VsH[w], vH1 = VsH[w + 4];
                unsigned vL0 = VsL[w], vL1 = VsL[w + 4];
                float* c = o[nd];
                mma_bf16(c[0], c[1], c[2], c[3], pH0, pH1, pH2, pH3, vL0, vL1);
                mma_bf16(c[0], c[1], c[2], c[3], pL0, pL1, pL2, pL3, vH0, vH1);
                mma_bf16(c[0], c[1], c[2], c[3], pH0, pH1, pH2, pH3, vH0, vH1);
            }
        }
        __syncthreads();   // smem reads done before next iter's cp.async overwrite
    }

    // softmax-then-scale quirk: /l AND /sqrt(DH)=8; write pre-split bf16 planes
    float inv0 = 1.f / (l0s * 8.f);
    float inv1 = 1.f / (l1s * 8.f);
#pragma unroll
    for (int nd = 0; nd < 8; nd++) {
        int cc = nd * 8 + 2 * tg;
        size_t o0 = (bL + r0) * DM + h * DH + cc;
        size_t o1 = (bL + r0 + 8) * DM + h * DH + cc;
        unsigned hu, lu;
        packsplit2(o[nd][0] * inv0, o[nd][1] * inv0, hu, lu);
        *(unsigned*)(attH + o0) = hu; *(unsigned*)(attL + o0) = lu;
        packsplit2(o[nd][2] * inv1, o[nd][3] * inv1, hu, lu);
        *(unsigned*)(attH + o1) = hu; *(unsigned*)(attL + o1) = lu;
    }
}

// ---------------- launch ----------------
extern "C" void kernel_launch(void* const* d_in, const int* in_sizes, int n_in,
                              void* d_out, int out_size)
{
    const float* q  = (const float*)d_in[0];
    const float* k  = (const float*)d_in[1];
    const float* v  = (const float*)d_in[2];
    // d_in[3] is the causal mask -> handled analytically
    const float* Wq = (const float*)d_in[4];
    const float* Wk = (const float*)d_in[5];
    const float* Wv = (const float*)d_in[6];
    const float* Wo = (const float*)d_in[7];
    float* out = (float*)d_out;

    auto gb = [](const void* sym) {
        void* p; cudaGetSymbolAddress(&p, sym); return (bf16*)p;
    };
    auto gf = [](const void* sym) {
        void* p; cudaGetSymbolAddress(&p, sym); return (float*)p;
    };
    bf16 *qH = gb(g_q_hi), *qL = gb(g_q_lo);
    bf16 *kH = gb(g_k_hi), *kL = gb(g_k_lo);
    bf16 *vH = gb(g_v_hi), *vL = gb(g_v_lo);
    bf16 *WqTH = gb(g_WqT_hi), *WqTL = gb(g_WqT_lo);
    bf16 *WkTH = gb(g_WkT_hi), *WkTL = gb(g_WkT_lo);
    bf16 *WvTH = gb(g_WvT_hi), *WvTL = gb(g_WvT_lo);
    bf16 *WoTH = gb(g_WoT_hi), *WoTL = gb(g_WoT_lo);
    bf16 *qhH = gb(g_qh_hi), *qhL = gb(g_qh_lo);
    bf16 *khH = gb(g_kh_hi), *khL = gb(g_kh_lo);
    float *vhR = gf(g_vh_raw);
    bf16 *vtH = gb(g_vt_hi), *vtL = gb(g_vt_lo);
    bf16 *attH = gb(g_att_hi), *attL = gb(g_att_lo);

    static int smem_set = 0;
    if (!smem_set) {
        cudaFuncSetAttribute(gemm_bf3, cudaFuncAttributeMaxDynamicSharedMemorySize, GEMM_SMEM);
        cudaFuncSetAttribute(attn_bf3, cudaFuncAttributeMaxDynamicSharedMemorySize, ATTN_SMEM);
        smem_set = 1;
    }

    // 1. split activations q,k,v into bf16 hi/lo planes
    SplitEnt eq = {q, qH, qL}, ek = {k, kH, kL}, ev = {v, vH, vL};
    split_acts<<<dim3(MROWS * DM / 4 / 256, 1, 3), 256>>>(eq, ek, ev);

    // 2. transpose+split the four weight matrices
    WBatch wb;
    wb.e[0] = {Wq, WqTH, WqTL};
    wb.e[1] = {Wk, WkTH, WkTL};
    wb.e[2] = {Wv, WvTH, WvTL};
    wb.e[3] = {Wo, WoTH, WoTL};
    wtrans<<<dim3(32, 32, 4), 256>>>(wb);

    // 3. projection GEMMs (batched): q,k -> split planes; v -> raw fp32
    GemmBatch gp;
    gp.e[0] = {qH, qL, WqTH, WqTL, qhH, qhL, nullptr, 1};
    gp.e[1] = {kH, kL, WkTH, WkTL, khH, khL, nullptr, 1};
    gp.e[2] = {vH, vL, WvTH, WvTL, nullptr, nullptr, vhR, 0};
    gemm_bf3<<<dim3(DM / GBN, MROWS / GBM, 3), 256, GEMM_SMEM>>>(gp, MROWS, DM, DM);

    // 4. transpose+split V per head: [b,L,h,d] -> [bh,d,L]
    vtrans<<<dim3(L_ / 32, DH / 32, B_ * H_), 256>>>(vhR, vtH, vtL);

    // 5. attention
    attn_bf3<<<dim3(L_ / TQ, B_ * H_), 128, ATTN_SMEM>>>(
        qhH, qhL, khH, khL, vtH, vtL, attH, attL);

    // 6. output GEMM -> raw fp32 d_out
    GemmBatch go;
    go.e[0] = {attH, attL, WoTH, WoTL, nullptr, nullptr, out, 0};
    go.e[1] = go.e[0];
    go.e[2] = go.e[0];
    gemm_bf3<<<dim3(DM / GBN, MROWS / GBM, 1), 256, GEMM_SMEM>>>(go, MROWS, DM, DM);
}